// round 9
// baseline (speedup 1.0000x reference)
#include <cuda_runtime.h>
#include <cuda_bf16.h>
#include <math.h>
#include <float.h>
#include <stdint.h>

// ---------------- problem constants ----------------
constexpr int Bq = 8, Eq = 256, Nq = 32;
constexpr int Dq = 512, RDq = 768, Rq = 2000;
constexpr int Lq = 2, Kq = 8, Mq = 32, Hq = 8, DHq = 64;
constexpr int HLLMq = 4096;
constexpr int BEq = Bq * Eq;          // 2048 edge tokens
constexpr int RPAD = 2048;            // rel rows padded to TM multiple
constexpr float EPSq = 1e-5f;

// ---------------- scratch (device globals; no allocs allowed) ----------------
__device__ float g_proj  [RPAD * Dq];
__device__ float g_states[BEq * Dq];
__device__ float g_t2    [BEq * Dq];
__device__ float g_kv    [BEq * 2 * Dq];   // [2048, 1024]: k | v
__device__ float g_kvb   [2 * Dq];
__device__ float g_q     [Mq * Dq];
__device__ float g_mem2  [Bq * Mq * Dq];
__device__ float g_noedge[Bq];
__device__ float g_vwT   [Lq][Dq * Dq];    // fp32 transpose of vw per layer
__device__ float g_cb    [Lq][Dq];         // folded attn bias
__device__ float g_zero512[Dq];            // never written: zero bias
// bf16 hi/lo split activation buffers
__device__ __align__(256) __nv_bfloat16 g_agg_h[BEq * Dq],      g_agg_l[BEq * Dq];
__device__ __align__(256) __nv_bfloat16 g_st_h [BEq * Dq],      g_st_l [BEq * Dq];
__device__ __align__(256) __nv_bfloat16 g_hid_h[BEq * 4 * Dq],  g_hid_l[BEq * 4 * Dq];
__device__ __align__(256) __nv_bfloat16 g_mem_h[Bq * Mq * Dq],  g_mem_l[Bq * Mq * Dq];
__device__ __align__(256) __nv_bfloat16 g_m2_h [Bq * Mq * Dq],  g_m2_l [Bq * Mq * Dq];
// bf16 hi/lo split weight buffers
__device__ __align__(256) __nv_bfloat16 g_emb_h[RPAD * RDq],     g_emb_l[RPAD * RDq]; // pad rows stay 0
__device__ __align__(256) __nv_bfloat16 g_rpw_h[Dq * RDq],       g_rpw_l[Dq * RDq];
__device__ __align__(256) __nv_bfloat16 g_ow_h[Lq][Dq * Dq],     g_ow_l[Lq][Dq * Dq];
__device__ __align__(256) __nv_bfloat16 g_vwT_h[Lq][Dq * Dq],    g_vwT_l[Lq][Dq * Dq];
__device__ __align__(256) __nv_bfloat16 g_wc_h[Lq][Dq * Dq],     g_wc_l[Lq][Dq * Dq];
__device__ __align__(256) __nv_bfloat16 g_w1_h[Lq][4 * Dq * Dq], g_w1_l[Lq][4 * Dq * Dq];
__device__ __align__(256) __nv_bfloat16 g_w2_h[Lq][4 * Dq * Dq], g_w2_l[Lq][4 * Dq * Dq];
__device__ __align__(256) __nv_bfloat16 g_kvw_h[2 * Dq * Dq],    g_kvw_l[2 * Dq * Dq];
__device__ __align__(256) __nv_bfloat16 g_to_h[Dq * Dq],         g_to_l[Dq * Dq];
__device__ __align__(256) __nv_bfloat16 g_pw_h[HLLMq * Dq],      g_pw_l[HLLMq * Dq];

__device__ __forceinline__ void splitw(float v, __nv_bfloat16* H, __nv_bfloat16* L, size_t i) {
    __nv_bfloat16 h = __float2bfloat16(v);
    H[i] = h;
    L[i] = __float2bfloat16(v - __bfloat162float(h));
}

__device__ __forceinline__ uint32_t smem_u32(const void* p) {
    uint32_t a;
    asm("{ .reg .u64 t; cvta.to.shared.u64 t, %1; cvt.u32.u64 %0, t; }" : "=r"(a) : "l"(p));
    return a;
}

// ---------------- reductions ----------------
__device__ __forceinline__ float warpSum(float v) {
    #pragma unroll
    for (int o = 16; o; o >>= 1) v += __shfl_xor_sync(0xffffffffu, v, o);
    return v;
}
__device__ __forceinline__ float warpMax(float v) {
    #pragma unroll
    for (int o = 16; o; o >>= 1) v = fmaxf(v, __shfl_xor_sync(0xffffffffu, v, o));
    return v;
}
__device__ __forceinline__ float blockSum(float v, float* red) {
    int lane = threadIdx.x & 31, w = threadIdx.x >> 5;
    int nw = blockDim.x >> 5;
    v = warpSum(v);
    if (lane == 0) red[w] = v;
    __syncthreads();
    if (w == 0) {
        float r = (lane < nw) ? red[lane] : 0.f;
        r = warpSum(r);
        if (lane == 0) red[0] = r;
    }
    __syncthreads();
    float out = red[0];
    __syncthreads();
    return out;
}
__device__ __forceinline__ float blockMax(float v, float* red) {
    int lane = threadIdx.x & 31, w = threadIdx.x >> 5;
    int nw = blockDim.x >> 5;
    v = warpMax(v);
    if (lane == 0) red[w] = v;
    __syncthreads();
    if (w == 0) {
        float r = (lane < nw) ? red[lane] : -FLT_MAX;
        r = warpMax(r);
        if (lane == 0) red[0] = r;
    }
    __syncthreads();
    float out = red[0];
    __syncthreads();
    return out;
}

// ---------------- mma.sync primitives ----------------
__device__ __forceinline__ void mma16816(float* d, const uint32_t* a, const uint32_t* b) {
    asm volatile("mma.sync.aligned.m16n8k16.row.col.f32.bf16.bf16.f32 "
        "{%0,%1,%2,%3}, {%4,%5,%6,%7}, {%8,%9}, {%0,%1,%2,%3};"
        : "+f"(d[0]), "+f"(d[1]), "+f"(d[2]), "+f"(d[3])
        : "r"(a[0]), "r"(a[1]), "r"(a[2]), "r"(a[3]), "r"(b[0]), "r"(b[1]));
}
__device__ __forceinline__ void ldsm4(uint32_t& r0, uint32_t& r1, uint32_t& r2, uint32_t& r3,
                                      uint32_t addr) {
    asm volatile("ldmatrix.sync.aligned.m8n8.x4.shared.b16 {%0,%1,%2,%3}, [%4];"
        : "=r"(r0), "=r"(r1), "=r"(r2), "=r"(r3) : "r"(addr));
}
__device__ __forceinline__ void cpasync16(uint32_t dst, const void* src) {
    asm volatile("cp.async.cg.shared.global [%0], [%1], 16;\n" :: "r"(dst), "l"(src) : "memory");
}

// ================= bf16x3 NT GEMM via mma.sync, BK=64, 4-stage pipeline =================
// C[M,N] = (Ah+Al)[M,K]*(Bh+Bl)[N,K]^T (terms AhBh+AhBl+AlBh) + bias (+res)(+gelu)
// M % TM == 0, N % TN == 0, K % 64 == 0, 3K/64 >= 3. 256 threads (8 warps).
// Fragment double-buffering across the 4 kh steps hides ldsm latency under mma.
constexpr int PADK = 72;   // 64 + 8: 144-byte row stride, 16B-aligned, ldmatrix conflict-free
constexpr int NSTG = 4;    // prefetch i+3, wait_group 2 (proven R6 pipeline)
constexpr int NTHR = 256;

template<int TM, int TN, int WR, int WC, int ACT, bool RES, bool WF32, bool WSPLIT>
__global__ __launch_bounds__(NTHR)
void mma_nt(const __nv_bfloat16* __restrict__ Ah, const __nv_bfloat16* __restrict__ Al,
            const __nv_bfloat16* __restrict__ Bh, const __nv_bfloat16* __restrict__ Bl,
            const float* __restrict__ bias, const float* __restrict__ res,
            float* __restrict__ Cf, __nv_bfloat16* __restrict__ Ch, __nv_bfloat16* __restrict__ Cl,
            int M, int N, int K)
{
    extern __shared__ __align__(128) __nv_bfloat16 smem[];
    constexpr int STG_E = (TM + TN) * PADK;
    constexpr int tm = TM / WR, tn = TN / WC;
    constexpr int MT = tm / 16, NT = tn / 8;

    const int tid = threadIdx.x;
    const int wid = tid >> 5, lane = tid & 31;
    const int bm = blockIdx.y * TM, bn = blockIdx.x * TN;
    const int wm = (wid / WC) * tm, wn = (wid % WC) * tn;
    const uint32_t sbase = smem_u32(smem);

    const int NI = (3 * K) / 64;

    auto load_stage = [&](int stage, int buf) {
        int c0 = stage * 64;
        int term = c0 / K;
        int kk = c0 - term * K;
        const __nv_bfloat16* As = (term < 2) ? Ah : Al;
        const __nv_bfloat16* Bs = (term == 1) ? Bl : Bh;
        uint32_t base = sbase + (uint32_t)buf * STG_E * 2;
        constexpr int CHA = TM * 8, CH = (TM + TN) * 8;
        #pragma unroll
        for (int j = 0; j < CH / NTHR; ++j) {
            int f = tid + NTHR * j;
            if (f < CHA) {
                int row = f >> 3, ch = f & 7;
                cpasync16(base + (uint32_t)(row * PADK + ch * 8) * 2,
                          As + (size_t)(bm + row) * K + kk + ch * 8);
            } else {
                int f2 = f - CHA;
                int row = f2 >> 3, ch = f2 & 7;
                cpasync16(base + (uint32_t)(TM * PADK + row * PADK + ch * 8) * 2,
                          Bs + (size_t)(bn + row) * K + kk + ch * 8);
            }
        }
        asm volatile("cp.async.commit_group;\n" ::: "memory");
    };

    float d[MT][NT][4];
    #pragma unroll
    for (int a = 0; a < MT; a++)
        #pragma unroll
        for (int b = 0; b < NT; b++)
            #pragma unroll
            for (int c = 0; c < 4; c++) d[a][b][c] = 0.f;

    load_stage(0, 0);
    load_stage(1, 1);
    load_stage(2, 2);

    const int a_lrow = lane & 15, a_lk = (lane >> 4) * 8;
    const int bq = lane >> 3;
    const int b_lrow = (lane & 7) + ((bq >> 1) * 8);
    const int b_lk = (bq & 1) * 8;

    // double-buffered fragments (registers)
    uint32_t afr[2][MT][4];
    uint32_t bfr[2][NT][2];

    auto ldfr = [&](uint32_t abase, uint32_t bbase, int kh, int buf) {
        const int kc = kh * 16;
        #pragma unroll
        for (int mt = 0; mt < MT; ++mt)
            ldsm4(afr[buf][mt][0], afr[buf][mt][1], afr[buf][mt][2], afr[buf][mt][3],
                  abase + (uint32_t)((wm + mt * 16 + a_lrow) * PADK + kc + a_lk) * 2);
        #pragma unroll
        for (int nt2 = 0; nt2 < NT / 2; ++nt2) {
            uint32_t r0, r1, r2, r3;
            ldsm4(r0, r1, r2, r3,
                  bbase + (uint32_t)((wn + nt2 * 16 + b_lrow) * PADK + kc + b_lk) * 2);
            bfr[buf][nt2 * 2][0] = r0; bfr[buf][nt2 * 2][1] = r1;
            bfr[buf][nt2 * 2 + 1][0] = r2; bfr[buf][nt2 * 2 + 1][1] = r3;
        }
    };

    for (int i = 0; i < NI; ++i) {
        if (i + 3 <= NI)      asm volatile("cp.async.wait_group 2;\n" ::: "memory");
        else if (i + 2 == NI) asm volatile("cp.async.wait_group 1;\n" ::: "memory");
        else                  asm volatile("cp.async.wait_group 0;\n" ::: "memory");
        __syncthreads();

        if (i + 3 < NI) load_stage(i + 3, (i + 3) & (NSTG - 1));

        const uint32_t abase = sbase + (uint32_t)(i & (NSTG - 1)) * STG_E * 2;
        const uint32_t bbase = abase + TM * PADK * 2;

        ldfr(abase, bbase, 0, 0);
        #pragma unroll
        for (int kh = 0; kh < 4; ++kh) {
            const int cur = kh & 1;
            if (kh < 3) ldfr(abase, bbase, kh + 1, cur ^ 1);   // prefetch next frags
            #pragma unroll
            for (int mt = 0; mt < MT; ++mt)
                #pragma unroll
                for (int nt = 0; nt < NT; ++nt)
                    mma16816(d[mt][nt], afr[cur][mt], bfr[cur][nt]);
        }
    }

    const int erow = lane >> 2, ecol = (lane & 3) * 2;
    #pragma unroll
    for (int mt = 0; mt < MT; ++mt) {
        #pragma unroll
        for (int h = 0; h < 2; ++h) {
            const int row = bm + wm + mt * 16 + erow + h * 8;
            #pragma unroll
            for (int nt = 0; nt < NT; ++nt) {
                const int n = bn + wn + nt * 8 + ecol;
                float v0 = d[mt][nt][h * 2 + 0];
                float v1 = d[mt][nt][h * 2 + 1];
                float2 bv = *(const float2*)(bias + n);
                v0 += bv.x; v1 += bv.y;
                if (RES) {
                    float2 rv = *(const float2*)(res + (size_t)row * N + n);
                    v0 += rv.x; v1 += rv.y;
                }
                if (ACT == 1) {
                    v0 = 0.5f * v0 * (1.0f + erff(v0 * 0.70710678118654752f));
                    v1 = 0.5f * v1 * (1.0f + erff(v1 * 0.70710678118654752f));
                }
                if (WF32)
                    *(float2*)(Cf + (size_t)row * N + n) = make_float2(v0, v1);
                if (WSPLIT) {
                    __nv_bfloat16 h0 = __float2bfloat16(v0), h1 = __float2bfloat16(v1);
                    __nv_bfloat16 l0 = __float2bfloat16(v0 - __bfloat162float(h0));
                    __nv_bfloat16 l1 = __float2bfloat16(v1 - __bfloat162float(h1));
                    uint32_t hp = ((uint32_t)__bfloat16_as_ushort(h1) << 16) | __bfloat16_as_ushort(h0);
                    uint32_t lp = ((uint32_t)__bfloat16_as_ushort(l1) << 16) | __bfloat16_as_ushort(l0);
                    *(uint32_t*)(Ch + (size_t)row * N + n) = hp;
                    *(uint32_t*)(Cl + (size_t)row * N + n) = lp;
                }
            }
        }
    }
}

// ---------------- fp32 SIMT NT GEMM (q-proj only) ----------------
template<int ACT, bool WF32, bool WSPLIT>
__global__ void gemm_nt(const float* __restrict__ A, const float* __restrict__ W,
                        const float* __restrict__ bias,
                        float* __restrict__ C, __nv_bfloat16* __restrict__ Ch,
                        __nv_bfloat16* __restrict__ Cl, int M, int N, int K)
{
    __shared__ float As[16][68];
    __shared__ float Ws[16][68];
    const int t  = threadIdx.x;
    const int bm = blockIdx.y * 64, bn = blockIdx.x * 64;
    const int lr = t >> 2, lk = (t & 3) * 4;
    const int ty = t >> 4, tx = t & 15;
    float acc[4][4] = {};

    for (int k0 = 0; k0 < K; k0 += 16) {
        int am = bm + lr;
        float4 av = make_float4(0.f, 0.f, 0.f, 0.f);
        if (am < M) av = *(const float4*)(A + (size_t)am * K + k0 + lk);
        As[lk + 0][lr] = av.x; As[lk + 1][lr] = av.y;
        As[lk + 2][lr] = av.z; As[lk + 3][lr] = av.w;
        int wn = bn + lr;
        float4 wv = make_float4(0.f, 0.f, 0.f, 0.f);
        if (wn < N) wv = *(const float4*)(W + (size_t)wn * K + k0 + lk);
        Ws[lk + 0][lr] = wv.x; Ws[lk + 1][lr] = wv.y;
        Ws[lk + 2][lr] = wv.z; Ws[lk + 3][lr] = wv.w;
        __syncthreads();
        #pragma unroll
        for (int kk = 0; kk < 16; kk++) {
            float4 a = *(const float4*)&As[kk][ty * 4];
            float4 b = *(const float4*)&Ws[kk][tx * 4];
            float av4[4] = {a.x, a.y, a.z, a.w};
            float bv4[4] = {b.x, b.y, b.z, b.w};
            #pragma unroll
            for (int i = 0; i < 4; i++)
                #pragma unroll
                for (int j = 0; j < 4; j++)
                    acc[i][j] += av4[i] * bv4[j];
        }
        __syncthreads();
    }
    #pragma unroll
    for (int i = 0; i < 4; i++) {
        int m = bm + ty * 4 + i;
        if (m >= M) continue;
        #pragma unroll
        for (int j = 0; j < 4; j++) {
            int n = bn + tx * 4 + j;
            if (n >= N) continue;
            float v = acc[i][j] + bias[n];
            if (ACT == 1) v = 0.5f * v * (1.0f + erff(v * 0.70710678118654752f));
            if (WF32) C[(size_t)m * N + n] = v;
            if (WSPLIT) splitw(v, Ch, Cl, (size_t)m * N + n);
        }
    }
}

// ---------------- fold prep (both layers via blockIdx.z) ----------------
__global__ void fold_prep_k(const float* __restrict__ vw0, const float* __restrict__ ow0,
                            const float* __restrict__ vb0, const float* __restrict__ ob0,
                            float* __restrict__ vwT0, float* __restrict__ cb0)
{
    const int lz = blockIdx.z;
    const float* vw = vw0 + (size_t)lz * Dq * Dq;
    const float* ow = ow0 + (size_t)lz * Dq * Dq;
    const float* vb = vb0 + lz * Dq;
    const float* ob = ob0 + lz * Dq;
    float* vwT = vwT0 + (size_t)lz * Dq * Dq;
    float* cb  = cb0 + lz * Dq;

    __shared__ float tile[32][33];
    const int bx = blockIdx.x, by = blockIdx.y;    // grid (16,16,L)
    const int t = threadIdx.x;
    const int tx = t & 31, ty = t >> 5;
    #pragma unroll
    for (int r = 0; r < 4; r++)
        tile[ty + r * 8][tx] = vw[(size_t)(by * 32 + ty + r * 8) * Dq + bx * 32 + tx];
    __syncthreads();
    #pragma unroll
    for (int r = 0; r < 4; r++)
        vwT[(size_t)(bx * 32 + ty + r * 8) * Dq + by * 32 + tx] = tile[tx][ty + r * 8];

    if (by == 0) {
        int n = bx * 32 + (t >> 3), ks = t & 7;
        float p = 0.f;
        for (int k = ks * 64; k < ks * 64 + 64; k++) p += ow[(size_t)n * Dq + k] * vb[k];
        p += __shfl_xor_sync(0xffffffffu, p, 1);
        p += __shfl_xor_sync(0xffffffffu, p, 2);
        p += __shfl_xor_sync(0xffffffffu, p, 4);
        if (ks == 0) cb[n] = p + ob[n];
    }
}

// ---------------- fused weight split ----------------
struct SplitSeg { const float* src; __nv_bfloat16* h; __nv_bfloat16* l; int n; };
struct SplitArgs { SplitSeg seg[14]; int total; };

__global__ void split_all_k(SplitArgs a) {
    int i = blockIdx.x * 256 + threadIdx.x;
    if (i >= a.total) return;
    int idx = i, s = 0;
    while (idx >= a.seg[s].n) { idx -= a.seg[s].n; s++; }
    splitw(a.seg[s].src[idx], a.seg[s].h, a.seg[s].l, idx);
}

// ---------------- sims + inline norms + top-k + agg(split) + states init ----------------
__global__ void sims_agg_k(const int* __restrict__ eids, const int* __restrict__ nids)
{
    int be = blockIdx.x, t = threadIdx.x;
    int lane = t & 31, w = t >> 5;
    __shared__ float se[Dq];
    __shared__ float ssim[Nq];
    __shared__ int   snid[Nq];
    __shared__ int   ssel[Kq];
    __shared__ float red[32];

    int eid = eids[be];
    float sq = 0.f;
    for (int d = t; d < Dq; d += 256) {
        float x = g_proj[eid * Dq + d];
        se[d] = x;
        g_states[(size_t)be * Dq + d] = x;
        sq += x * x;
    }
    float en = fmaxf(sqrtf(blockSum(sq, red)), 1e-12f);

    for (int n = w; n < Nq; n += 8) {
        int nid = nids[be * Nq + n];
        float s = 0.f, q = 0.f;
        for (int d = lane; d < Dq; d += 32) {
            float p = g_proj[nid * Dq + d];
            s += p * se[d];
            q += p * p;
        }
        s = warpSum(s); q = warpSum(q);
        if (lane == 0) {
            snid[n] = nid;
            ssim[n] = s / (fmaxf(sqrtf(q), 1e-12f) * en);
        }
    }
    __syncthreads();

    if (w == 0) {
        float sv = ssim[lane];
        for (int it = 0; it < Kq; it++) {
            float bs = sv; int bi = lane;
            #pragma unroll
            for (int o = 16; o; o >>= 1) {
                float os = __shfl_xor_sync(0xffffffffu, bs, o);
                int   oi = __shfl_xor_sync(0xffffffffu, bi, o);
                if (os > bs || (os == bs && oi < bi)) { bs = os; bi = oi; }
            }
            if (lane == bi) sv = -FLT_MAX;
            if (lane == 0) ssel[it] = snid[bi];
        }
    }
    __syncthreads();

    for (int d = t; d < Dq; d += 256) {
        float a = 0.f;
        #pragma unroll
        for (int k2 = 0; k2 < Kq; k2++) a += g_proj[ssel[k2] * Dq + d];
        splitw(a * (1.0f / Kq), g_agg_h, g_agg_l, (size_t)be * Dq + d);
    }
}

// ---------------- layernorm -> fp32 states + hi/lo split ----------------
template<bool MASK>
__global__ void ln_k(const float* __restrict__ in, const float* __restrict__ g,
                     const float* __restrict__ b, const float* __restrict__ mask,
                     float* __restrict__ out, __nv_bfloat16* __restrict__ oh,
                     __nv_bfloat16* __restrict__ ol)
{
    int be = blockIdx.x, t = threadIdx.x;
    __shared__ float red[32];
    const float* x = in + (size_t)be * Dq;
    float v0 = x[t], v1 = x[t + 256];
    float mu = blockSum(v0 + v1, red) * (1.0f / Dq);
    float d0 = v0 - mu, d1 = v1 - mu;
    float var = blockSum(d0 * d0 + d1 * d1, red) * (1.0f / Dq);
    float r = rsqrtf(var + EPSq);
    float mk = MASK ? mask[be] : 1.0f;
    float o0 = (d0 * r * g[t      ] + b[t      ]) * mk;
    float o1 = (d1 * r * g[t + 256] + b[t + 256]) * mk;
    size_t i0 = (size_t)be * Dq + t, i1 = i0 + 256;
    out[i0] = o0; out[i1] = o1;
    splitw(o0, oh, ol, i0);
    splitw(o1, oh, ol, i1);
}

// ---------------- pack kv bias ----------------
__global__ void pack_kvb_k(const float* __restrict__ kb, const float* __restrict__ vb) {
    int i = blockIdx.x * 256 + threadIdx.x;    // 1024
    g_kvb[i] = (i < Dq) ? kb[i] : vb[i - Dq];
}

// ---------------- no-edge flags ----------------
__global__ void noedge_k(const float* __restrict__ mask) {
    int b = blockIdx.x;
    __shared__ float red[32];
    float s = blockSum(mask[b * Eq + threadIdx.x], red);
    if (threadIdx.x == 0) g_noedge[b] = (s == 0.f) ? 0.f : 1.f;
}

// ---------------- memory-token cross attention, head-parallel ----------------
__global__ void attn_k(const float* __restrict__ mask)
{
    int bmh = blockIdx.x;                    // B*M*H = 2048
    int h = bmh & 7, bm = bmh >> 3;
    int b = bm >> 5, m = bm & 31;
    int t = threadIdx.x;
    __shared__ float qh[DHq];
    __shared__ float sc[Eq];
    __shared__ float red[32];
    __shared__ float outp[4][DHq];

    if (t < DHq) qh[t] = g_q[m * Dq + h * DHq + t];
    __syncthreads();

    const float* kr = g_kv + (size_t)(b * Eq + t) * (2 * Dq) + h * DHq;
    float dot = 0.f;
    #pragma unroll
    for (int d = 0; d < DHq; d++) dot += qh[d] * kr[d];
    float s = dot * 0.125f;
    if (mask[b * Eq + t] == 0.f) s = -FLT_MAX;

    float mx = blockMax(s, red);
    float e = expf(s - mx);
    sc[t] = e;
    float sum = blockSum(e, red);

    int d = t & 63, gp = t >> 6;
    const float* vb0 = g_kv + (size_t)(b * Eq) * (2 * Dq) + Dq + h * DHq + d;
    float acc = 0.f;
    #pragma unroll 4
    for (int e2 = gp * 64; e2 < gp * 64 + 64; e2++)
        acc += sc[e2] * vb0[(size_t)e2 * (2 * Dq)];
    outp[gp][d] = acc;
    __syncthreads();
    if (t < DHq) {
        float o = (outp[0][t] + outp[1][t] + outp[2][t] + outp[3][t]) / sum;
        splitw(o, g_mem_h, g_mem_l, (size_t)bm * Dq + h * DHq + t);
    }
}

// ---------------- no-edge mask + split for final proj ----------------
__global__ void memmask_k() {
    int i = blockIdx.x * 256 + threadIdx.x;
    int b = i / (Mq * Dq);
    splitw(g_mem2[i] * g_noedge[b], g_m2_h, g_m2_l, i);
}

// ---------------- launch ----------------
extern "C" void kernel_launch(void* const* d_in, const int* in_sizes, int n_in,
                              void* d_out, int out_size)
{
    const int*   edge_ids  = (const int*)  d_in[0];
    const int*   neigh_ids = (const int*)  d_in[1];
    const float* edge_mask = (const float*)d_in[2];
    const float* rel_emb   = (const float*)d_in[3];
    const float* rp_w      = (const float*)d_in[4];
    const float* rp_b      = (const float*)d_in[5];
    const float* ly_vw     = (const float*)d_in[6];
    const float* ly_vb     = (const float*)d_in[7];
    const float* ly_ow     = (const float*)d_in[8];
    const float* ly_ob     = (const float*)d_in[9];
    const float* ly_n1g    = (const float*)d_in[10];
    const float* ly_n1b    = (const float*)d_in[11];
    const float* ly_n2g    = (const float*)d_in[12];
    const float* ly_n2b    = (const float*)d_in[13];
    const float* ly_w1     = (const float*)d_in[14];
    const float* ly_b1     = (const float*)d_in[15];
    const float* ly_w2     = (const float*)d_in[16];
    const float* ly_b2     = (const float*)d_in[17];
    const float* mem_q     = (const float*)d_in[18];
    const float* t_qw      = (const float*)d_in[19];
    const float* t_qb      = (const float*)d_in[20];
    const float* t_kw      = (const float*)d_in[21];
    const float* t_kb      = (const float*)d_in[22];
    const float* t_vw      = (const float*)d_in[23];
    const float* t_vb      = (const float*)d_in[24];
    const float* t_ow      = (const float*)d_in[25];
    const float* t_ob      = (const float*)d_in[26];
    const float* proj_w    = (const float*)d_in[27];
    const float* proj_b    = (const float*)d_in[28];
    float* out = (float*)d_out;

    float *p_proj, *p_states, *p_t2, *p_kv, *p_kvb, *p_q, *p_mem2, *p_vwT, *p_cb, *p_zero;
    cudaGetSymbolAddress((void**)&p_proj,   g_proj);
    cudaGetSymbolAddress((void**)&p_states, g_states);
    cudaGetSymbolAddress((void**)&p_t2,     g_t2);
    cudaGetSymbolAddress((void**)&p_kv,     g_kv);
    cudaGetSymbolAddress((void**)&p_kvb,    g_kvb);
    cudaGetSymbolAddress((void**)&p_q,      g_q);
    cudaGetSymbolAddress((void**)&p_mem2,   g_mem2);
    cudaGetSymbolAddress((void**)&p_vwT,    g_vwT);
    cudaGetSymbolAddress((void**)&p_cb,     g_cb);
    cudaGetSymbolAddress((void**)&p_zero,   g_zero512);

    __nv_bfloat16 *p_agg_h, *p_agg_l, *p_st_h, *p_st_l, *p_hid_h, *p_hid_l;
    __nv_bfloat16 *p_mem_h, *p_mem_l, *p_m2_h, *p_m2_l;
    cudaGetSymbolAddress((void**)&p_agg_h,  g_agg_h);
    cudaGetSymbolAddress((void**)&p_agg_l,  g_agg_l);
    cudaGetSymbolAddress((void**)&p_st_h,   g_st_h);
    cudaGetSymbolAddress((void**)&p_st_l,   g_st_l);
    cudaGetSymbolAddress((void**)&p_hid_h,  g_hid_h);
    cudaGetSymbolAddress((void**)&p_hid_l,  g_hid_l);
    cudaGetSymbolAddress((void**)&p_mem_h,  g_mem_h);
    cudaGetSymbolAddress((void**)&p_mem_l,  g_mem_l);
    cudaGetSymbolAddress((void**)&p_m2_h,   g_m2_h);
    cudaGetSymbolAddress((void**)&p_m2_l,   g_m2_l);

    __nv_bfloat16 *p_emb_h, *p_emb_l, *p_rpw_h, *p_rpw_l, *p_ow_h, *p_ow_l, *p_vwT_h, *p_vwT_l;
    __nv_bfloat16 *p_wc_h, *p_wc_l, *p_w1_h, *p_w1_l, *p_w2_h, *p_w2_l;
    __nv_bfloat16 *p_kvw_h, *p_kvw_l, *p_to_h, *p_to_l, *p_pw_h, *p_pw_l;
    cudaGetSymbolAddress((void**)&p_emb_h, g_emb_h);
    cudaGetSymbolAddress((void**)&p_emb_l, g_emb_l);
    cudaGetSymbolAddress((void**)&p_rpw_h, g_rpw_h);
    cudaGetSymbolAddress((void**)&p_rpw_l, g_rpw_l);
    cudaGetSymbolAddress((void**)&p_ow_h,  g_ow_h);
    cudaGetSymbolAddress((void**)&p_ow_l,  g_ow_l);
    cudaGetSymbolAddress((void**)&p_vwT_h, g_vwT_h);
    cudaGetSymbolAddress((void**)&p_vwT_l, g_vwT_l);
    cudaGetSymbolAddress((void**)&p_wc_h,  g_wc_h);
    cudaGetSymbolAddress((void**)&p_wc_l,  g_wc_l);
    cudaGetSymbolAddress((void**)&p_w1_h,  g_w1_h);
    cudaGetSymbolAddress((void**)&p_w1_l,  g_w1_l);
    cudaGetSymbolAddress((void**)&p_w2_h,  g_w2_h);
    cudaGetSymbolAddress((void**)&p_w2_l,  g_w2_l);
    cudaGetSymbolAddress((void**)&p_kvw_h, g_kvw_h);
    cudaGetSymbolAddress((void**)&p_kvw_l, g_kvw_l);
    cudaGetSymbolAddress((void**)&p_to_h,  g_to_h);
    cudaGetSymbolAddress((void**)&p_to_l,  g_to_l);
    cudaGetSymbolAddress((void**)&p_pw_h,  g_pw_h);
    cudaGetSymbolAddress((void**)&p_pw_l,  g_pw_l);

    constexpr int DD = Dq * Dq, DD4 = 4 * Dq * Dq;

    auto kA = mma_nt<128,64,4,2, 0,false,false,true>;   // split out (Wc)
    auto kB = mma_nt<128,64,4,2, 0,true ,true ,false>;  // res + f32 out
    auto kC = mma_nt<128,128,2,4, 1,false,false,true>;  // gelu + split out
    auto kD = mma_nt<128,64,4,2, 0,false,true ,false>;  // f32 out
    constexpr int SM64  = (128 + 64)  * PADK * 2 * NSTG;  // 110,592
    constexpr int SM128 = (128 + 128) * PADK * 2 * NSTG;  // 147,456
    cudaFuncSetAttribute(kA, cudaFuncAttributeMaxDynamicSharedMemorySize, SM64);
    cudaFuncSetAttribute(kB, cudaFuncAttributeMaxDynamicSharedMemorySize, SM64);
    cudaFuncSetAttribute(kC, cudaFuncAttributeMaxDynamicSharedMemorySize, SM128);
    cudaFuncSetAttribute(kD, cudaFuncAttributeMaxDynamicSharedMemorySize, SM64);

    // (1) fold prep both layers
    fold_prep_k<<<dim3(16,16,Lq), 256>>>(ly_vw, ly_ow, ly_vb, ly_ob, p_vwT, p_cb);

    // (2) fused splits (14 segments; g_emb pad rows stay zero from static init)
    {
        SplitArgs sa;
        int s = 0, tot = 0;
        auto add = [&](const float* src, __nv_bfloat16* h, __nv_bfloat16* l, int n) {
            sa.seg[s++] = SplitSeg{src, h, l, n}; tot += n;
        };
        for (int l = 0; l < Lq; l++) {
            add(ly_w1 + (size_t)l * DD4, p_w1_h + (size_t)l * DD4, p_w1_l + (size_t)l * DD4, DD4);
            add(ly_w2 + (size_t)l * DD4, p_w2_h + (size_t)l * DD4, p_w2_l + (size_t)l * DD4, DD4);
            add(ly_ow + (size_t)l * DD,  p_ow_h + (size_t)l * DD,  p_ow_l + (size_t)l * DD,  DD);
            add(p_vwT + (size_t)l * DD,  p_vwT_h + (size_t)l * DD, p_vwT_l + (size_t)l * DD, DD);
        }
        add(t_kw,    p_kvw_h,      p_kvw_l,      DD);
        add(t_vw,    p_kvw_h + DD, p_kvw_l + DD, DD);
        add(t_ow,    p_to_h,       p_to_l,       DD);
        add(proj_w,  p_pw_h,       p_pw_l,       HLLMq * Dq);
        add(rel_emb, p_emb_h,      p_emb_l,      Rq * RDq);
        add(rp_w,    p_rpw_h,      p_rpw_l,      Dq * RDq);
        sa.total = tot;
        split_all_k<<<(tot + 255) / 256, 256>>>(sa);
    }

    // (3) q-proj (tiny fp32)
    gemm_nt<0,true,false><<<dim3(Dq/64, 1), 256>>>(mem_q, t_qw, t_qb, p_q, nullptr, nullptr,
                                                   Mq, Dq, Dq);

    // (4) relation projection (bf16x3) — ncu profile slot
    kD<<<dim3(Dq/64, RPAD/128), NTHR, SM64>>>(
        p_emb_h, p_emb_l, p_rpw_h, p_rpw_l, rp_b, nullptr, p_proj, nullptr, nullptr,
        RPAD, Dq, RDq);

    // (5,6) Wc = ow @ vw (bf16x3) per layer
    for (int l = 0; l < Lq; l++)
        kA<<<dim3(Dq/64, Dq/128), NTHR, SM64>>>(
            p_ow_h + (size_t)l*DD, p_ow_l + (size_t)l*DD,
            p_vwT_h + (size_t)l*DD, p_vwT_l + (size_t)l*DD,
            p_zero, nullptr, nullptr, p_wc_h + (size_t)l*DD, p_wc_l + (size_t)l*DD, Dq, Dq, Dq);

    // misc prep
    pack_kvb_k<<<4, 256>>>(t_kb, t_vb);
    noedge_k<<<Bq, 256>>>(edge_mask);

    // sims + top-k + agg + states init
    sims_agg_k<<<BEq, 256>>>(edge_ids, neigh_ids);

    // relation-context layers
    for (int l = 0; l < Lq; l++) {
        kB<<<dim3(Dq/64, BEq/128), NTHR, SM64>>>(
            p_agg_h, p_agg_l, p_wc_h + (size_t)l*DD, p_wc_l + (size_t)l*DD,
            p_cb + l*Dq, p_states, p_t2, nullptr, nullptr, BEq, Dq, Dq);
        ln_k<false><<<BEq, 256>>>(p_t2, ly_n1g + l*Dq, ly_n1b + l*Dq, nullptr,
                                  p_states, p_st_h, p_st_l);

        kC<<<dim3(4*Dq/128, BEq/128), NTHR, SM128>>>(
            p_st_h, p_st_l, p_w1_h + (size_t)l*DD4, p_w1_l + (size_t)l*DD4,
            ly_b1 + l*4*Dq, nullptr, nullptr, p_hid_h, p_hid_l, BEq, 4*Dq, Dq);

        kB<<<dim3(Dq/64, BEq/128), NTHR, SM64>>>(
            p_hid_h, p_hid_l, p_w2_h + (size_t)l*DD4, p_w2_l + (size_t)l*DD4,
            ly_b2 + l*Dq, p_states, p_t2, nullptr, nullptr, BEq, Dq, 4*Dq);
        ln_k<true><<<BEq, 256>>>(p_t2, ly_n2g + l*Dq, ly_n2b + l*Dq, edge_mask,
                                 p_states, p_st_h, p_st_l);
    }

    // tokenizer K|V projection (combined)
    kD<<<dim3(2*Dq/64, BEq/128), NTHR, SM64>>>(
        p_st_h, p_st_l, p_kvw_h, p_kvw_l, p_kvb, nullptr, p_kv, nullptr, nullptr, BEq, 2*Dq, Dq);

    // attention + output proj + masking
    attn_k<<<Bq * Mq * Hq, 256>>>(edge_mask);
    kD<<<dim3(Dq/64, (Bq*Mq)/128), NTHR, SM64>>>(
        p_mem_h, p_mem_l, p_to_h, p_to_l, t_ob, nullptr, p_mem2, nullptr, nullptr, Bq*Mq, Dq, Dq);
    memmask_k<<<(Bq*Mq*Dq)/256, 256>>>();

    // LLM projection -> d_out
    kD<<<dim3(HLLMq/64, (Bq*Mq)/128), NTHR, SM64>>>(
        p_m2_h, p_m2_l, p_pw_h, p_pw_l, proj_b, nullptr, out, nullptr, nullptr, Bq*Mq, HLLMq, Dq);
}

// round 10
// speedup vs baseline: 1.3770x; 1.3770x over previous
#include <cuda_runtime.h>
#include <cuda_bf16.h>
#include <math.h>
#include <float.h>
#include <stdint.h>

// ---------------- problem constants ----------------
constexpr int Bq = 8, Eq = 256, Nq = 32;
constexpr int Dq = 512, RDq = 768, Rq = 2000;
constexpr int Lq = 2, Kq = 8, Mq = 32, Hq = 8, DHq = 64;
constexpr int HLLMq = 4096;
constexpr int BEq = Bq * Eq;          // 2048 edge tokens
constexpr int RPAD = 2048;            // rel rows padded to TM multiple
constexpr float EPSq = 1e-5f;

// ---------------- scratch (device globals; no allocs allowed) ----------------
__device__ float g_proj  [RPAD * Dq];
__device__ float g_states[BEq * Dq];
__device__ float g_t2    [BEq * Dq];
__device__ float g_kv    [BEq * 2 * Dq];   // [2048, 1024]: k | v
__device__ float g_kvb   [2 * Dq];
__device__ float g_q     [Mq * Dq];
__device__ float g_mem2  [Bq * Mq * Dq];
__device__ float g_noedge[Bq];
__device__ float g_vwT   [Lq][Dq * Dq];    // fp32 transpose of vw per layer
__device__ float g_cb    [Lq][Dq];         // folded attn bias
__device__ float g_zero512[Dq];            // never written: zero bias
// bf16 hi/lo split activation buffers
__device__ __align__(256) __nv_bfloat16 g_agg_h[BEq * Dq],      g_agg_l[BEq * Dq];
__device__ __align__(256) __nv_bfloat16 g_st_h [BEq * Dq],      g_st_l [BEq * Dq];
__device__ __align__(256) __nv_bfloat16 g_hid_h[BEq * 4 * Dq],  g_hid_l[BEq * 4 * Dq];
__device__ __align__(256) __nv_bfloat16 g_mem_h[Bq * Mq * Dq],  g_mem_l[Bq * Mq * Dq];
__device__ __align__(256) __nv_bfloat16 g_m2_h [Bq * Mq * Dq],  g_m2_l [Bq * Mq * Dq];
// bf16 hi/lo split weight buffers
__device__ __align__(256) __nv_bfloat16 g_emb_h[RPAD * RDq],     g_emb_l[RPAD * RDq]; // pad rows stay 0
__device__ __align__(256) __nv_bfloat16 g_rpw_h[Dq * RDq],       g_rpw_l[Dq * RDq];
__device__ __align__(256) __nv_bfloat16 g_ow_h[Lq][Dq * Dq],     g_ow_l[Lq][Dq * Dq];
__device__ __align__(256) __nv_bfloat16 g_vwT_h[Lq][Dq * Dq],    g_vwT_l[Lq][Dq * Dq];
__device__ __align__(256) __nv_bfloat16 g_wc_h[Lq][Dq * Dq],     g_wc_l[Lq][Dq * Dq];
__device__ __align__(256) __nv_bfloat16 g_w1_h[Lq][4 * Dq * Dq], g_w1_l[Lq][4 * Dq * Dq];
__device__ __align__(256) __nv_bfloat16 g_w2_h[Lq][4 * Dq * Dq], g_w2_l[Lq][4 * Dq * Dq];
__device__ __align__(256) __nv_bfloat16 g_kvw_h[2 * Dq * Dq],    g_kvw_l[2 * Dq * Dq];
__device__ __align__(256) __nv_bfloat16 g_to_h[Dq * Dq],         g_to_l[Dq * Dq];
__device__ __align__(256) __nv_bfloat16 g_pw_h[HLLMq * Dq],      g_pw_l[HLLMq * Dq];

__device__ __forceinline__ void splitw(float v, __nv_bfloat16* H, __nv_bfloat16* L, size_t i) {
    __nv_bfloat16 h = __float2bfloat16(v);
    H[i] = h;
    L[i] = __float2bfloat16(v - __bfloat162float(h));
}

__device__ __forceinline__ uint32_t smem_u32(const void* p) {
    uint32_t a;
    asm("{ .reg .u64 t; cvta.to.shared.u64 t, %1; cvt.u32.u64 %0, t; }" : "=r"(a) : "l"(p));
    return a;
}

// ---------------- reductions ----------------
__device__ __forceinline__ float warpSum(float v) {
    #pragma unroll
    for (int o = 16; o; o >>= 1) v += __shfl_xor_sync(0xffffffffu, v, o);
    return v;
}
__device__ __forceinline__ float warpMax(float v) {
    #pragma unroll
    for (int o = 16; o; o >>= 1) v = fmaxf(v, __shfl_xor_sync(0xffffffffu, v, o));
    return v;
}
__device__ __forceinline__ float blockSum(float v, float* red) {
    int lane = threadIdx.x & 31, w = threadIdx.x >> 5;
    int nw = blockDim.x >> 5;
    v = warpSum(v);
    if (lane == 0) red[w] = v;
    __syncthreads();
    if (w == 0) {
        float r = (lane < nw) ? red[lane] : 0.f;
        r = warpSum(r);
        if (lane == 0) red[0] = r;
    }
    __syncthreads();
    float out = red[0];
    __syncthreads();
    return out;
}
__device__ __forceinline__ float blockMax(float v, float* red) {
    int lane = threadIdx.x & 31, w = threadIdx.x >> 5;
    int nw = blockDim.x >> 5;
    v = warpMax(v);
    if (lane == 0) red[w] = v;
    __syncthreads();
    if (w == 0) {
        float r = (lane < nw) ? red[lane] : -FLT_MAX;
        r = warpMax(r);
        if (lane == 0) red[0] = r;
    }
    __syncthreads();
    float out = red[0];
    __syncthreads();
    return out;
}

// ---------------- mma.sync primitives ----------------
__device__ __forceinline__ void mma16816(float* d, const uint32_t* a, const uint32_t* b) {
    asm volatile("mma.sync.aligned.m16n8k16.row.col.f32.bf16.bf16.f32 "
        "{%0,%1,%2,%3}, {%4,%5,%6,%7}, {%8,%9}, {%0,%1,%2,%3};"
        : "+f"(d[0]), "+f"(d[1]), "+f"(d[2]), "+f"(d[3])
        : "r"(a[0]), "r"(a[1]), "r"(a[2]), "r"(a[3]), "r"(b[0]), "r"(b[1]));
}
__device__ __forceinline__ void ldsm4(uint32_t& r0, uint32_t& r1, uint32_t& r2, uint32_t& r3,
                                      uint32_t addr) {
    asm volatile("ldmatrix.sync.aligned.m8n8.x4.shared.b16 {%0,%1,%2,%3}, [%4];"
        : "=r"(r0), "=r"(r1), "=r"(r2), "=r"(r3) : "r"(addr));
}
__device__ __forceinline__ void cpasync16(uint32_t dst, const void* src) {
    asm volatile("cp.async.cg.shared.global [%0], [%1], 16;\n" :: "r"(dst), "l"(src) : "memory");
}

// ================= bf16x3 NT GEMM via mma.sync, BK=64, 4-stage pipeline =================
// C[M,N] = (Ah+Al)[M,K]*(Bh+Bl)[N,K]^T (terms AhBh+AhBl+AlBh) + bias (+res)(+gelu)
// M % TM == 0, N % TN == 0, K % 64 == 0, 3K/64 >= 3.
// Simple R6 inner loop (no manual fragment buffering). Block size is a template param:
// 512 thr (4,4) for TN=64 shapes (latency-bound, grid<=148), 256 thr (2,4) for TN=128.
constexpr int PADK = 72;   // 64 + 8: 144-byte row stride, 16B-aligned, ldmatrix conflict-free
constexpr int NSTG = 4;    // prefetch i+3, wait_group 2 (proven R6 pipeline)

template<int TM, int TN, int WR, int WC, int NTHR, int ACT, bool RES, bool WF32, bool WSPLIT>
__global__ __launch_bounds__(NTHR)
void mma_nt(const __nv_bfloat16* __restrict__ Ah, const __nv_bfloat16* __restrict__ Al,
            const __nv_bfloat16* __restrict__ Bh, const __nv_bfloat16* __restrict__ Bl,
            const float* __restrict__ bias, const float* __restrict__ res,
            float* __restrict__ Cf, __nv_bfloat16* __restrict__ Ch, __nv_bfloat16* __restrict__ Cl,
            int M, int N, int K)
{
    static_assert(WR * WC == NTHR / 32, "warp grid must cover block");
    extern __shared__ __align__(128) __nv_bfloat16 smem[];
    constexpr int STG_E = (TM + TN) * PADK;
    constexpr int tm = TM / WR, tn = TN / WC;
    constexpr int MT = tm / 16, NT = tn / 8;

    const int tid = threadIdx.x;
    const int wid = tid >> 5, lane = tid & 31;
    const int bm = blockIdx.z * gridDim.y * TM + blockIdx.y * TM;   // z used for batched Wc
    const int bn = blockIdx.x * TN;
    const int wm = (wid / WC) * tm, wn = (wid % WC) * tn;
    const uint32_t sbase = smem_u32(smem);

    const int NI = (3 * K) / 64;

    auto load_stage = [&](int stage, int buf) {
        int c0 = stage * 64;
        int term = c0 / K;
        int kk = c0 - term * K;
        const __nv_bfloat16* As = (term < 2) ? Ah : Al;
        const __nv_bfloat16* Bs = (term == 1) ? Bl : Bh;
        uint32_t base = sbase + (uint32_t)buf * STG_E * 2;
        constexpr int CHA = TM * 8, CH = (TM + TN) * 8;
        #pragma unroll
        for (int j = 0; j < CH / NTHR; ++j) {
            int f = tid + NTHR * j;
            if (f < CHA) {
                int row = f >> 3, ch = f & 7;
                cpasync16(base + (uint32_t)(row * PADK + ch * 8) * 2,
                          As + (size_t)(bm + row) * K + kk + ch * 8);
            } else {
                int f2 = f - CHA;
                int row = f2 >> 3, ch = f2 & 7;
                cpasync16(base + (uint32_t)(TM * PADK + row * PADK + ch * 8) * 2,
                          Bs + (size_t)(bn + row) * K + kk + ch * 8);
            }
        }
        asm volatile("cp.async.commit_group;\n" ::: "memory");
    };

    float d[MT][NT][4];
    #pragma unroll
    for (int a = 0; a < MT; a++)
        #pragma unroll
        for (int b = 0; b < NT; b++)
            #pragma unroll
            for (int c = 0; c < 4; c++) d[a][b][c] = 0.f;

    load_stage(0, 0);
    load_stage(1, 1);
    load_stage(2, 2);

    const int a_lrow = lane & 15, a_lk = (lane >> 4) * 8;
    const int bq = lane >> 3;
    const int b_lrow = (lane & 7) + ((bq >> 1) * 8);
    const int b_lk = (bq & 1) * 8;

    for (int i = 0; i < NI; ++i) {
        if (i + 3 <= NI)      asm volatile("cp.async.wait_group 2;\n" ::: "memory");
        else if (i + 2 == NI) asm volatile("cp.async.wait_group 1;\n" ::: "memory");
        else                  asm volatile("cp.async.wait_group 0;\n" ::: "memory");
        __syncthreads();

        if (i + 3 < NI) load_stage(i + 3, (i + 3) & (NSTG - 1));

        const uint32_t abase = sbase + (uint32_t)(i & (NSTG - 1)) * STG_E * 2;
        const uint32_t bbase = abase + TM * PADK * 2;

        #pragma unroll
        for (int kh = 0; kh < 4; ++kh) {
            const int kc = kh * 16;
            uint32_t afr[MT][4];
            #pragma unroll
            for (int mt = 0; mt < MT; ++mt)
                ldsm4(afr[mt][0], afr[mt][1], afr[mt][2], afr[mt][3],
                      abase + (uint32_t)((wm + mt * 16 + a_lrow) * PADK + kc + a_lk) * 2);
            uint32_t bfr[NT][2];
            #pragma unroll
            for (int nt2 = 0; nt2 < NT / 2; ++nt2) {
                uint32_t r0, r1, r2, r3;
                ldsm4(r0, r1, r2, r3,
                      bbase + (uint32_t)((wn + nt2 * 16 + b_lrow) * PADK + kc + b_lk) * 2);
                bfr[nt2 * 2][0] = r0; bfr[nt2 * 2][1] = r1;
                bfr[nt2 * 2 + 1][0] = r2; bfr[nt2 * 2 + 1][1] = r3;
            }
            #pragma unroll
            for (int mt = 0; mt < MT; ++mt)
                #pragma unroll
                for (int nt = 0; nt < NT; ++nt)
                    mma16816(d[mt][nt], afr[mt], bfr[nt]);
        }
    }

    const int erow = lane >> 2, ecol = (lane & 3) * 2;
    #pragma unroll
    for (int mt = 0; mt < MT; ++mt) {
        #pragma unroll
        for (int h = 0; h < 2; ++h) {
            const int row = bm + wm + mt * 16 + erow + h * 8;
            #pragma unroll
            for (int nt = 0; nt < NT; ++nt) {
                const int n = bn + wn + nt * 8 + ecol;
                float v0 = d[mt][nt][h * 2 + 0];
                float v1 = d[mt][nt][h * 2 + 1];
                float2 bv = *(const float2*)(bias + n);
                v0 += bv.x; v1 += bv.y;
                if (RES) {
                    float2 rv = *(const float2*)(res + (size_t)row * N + n);
                    v0 += rv.x; v1 += rv.y;
                }
                if (ACT == 1) {
                    v0 = 0.5f * v0 * (1.0f + erff(v0 * 0.70710678118654752f));
                    v1 = 0.5f * v1 * (1.0f + erff(v1 * 0.70710678118654752f));
                }
                if (WF32)
                    *(float2*)(Cf + (size_t)row * N + n) = make_float2(v0, v1);
                if (WSPLIT) {
                    __nv_bfloat16 h0 = __float2bfloat16(v0), h1 = __float2bfloat16(v1);
                    __nv_bfloat16 l0 = __float2bfloat16(v0 - __bfloat162float(h0));
                    __nv_bfloat16 l1 = __float2bfloat16(v1 - __bfloat162float(h1));
                    uint32_t hp = ((uint32_t)__bfloat16_as_ushort(h1) << 16) | __bfloat16_as_ushort(h0);
                    uint32_t lp = ((uint32_t)__bfloat16_as_ushort(l1) << 16) | __bfloat16_as_ushort(l0);
                    *(uint32_t*)(Ch + (size_t)row * N + n) = hp;
                    *(uint32_t*)(Cl + (size_t)row * N + n) = lp;
                }
            }
        }
    }
}

// ---------------- fp32 SIMT NT GEMM (q-proj only) ----------------
template<int ACT, bool WF32, bool WSPLIT>
__global__ void gemm_nt(const float* __restrict__ A, const float* __restrict__ W,
                        const float* __restrict__ bias,
                        float* __restrict__ C, __nv_bfloat16* __restrict__ Ch,
                        __nv_bfloat16* __restrict__ Cl, int M, int N, int K)
{
    __shared__ float As[16][68];
    __shared__ float Ws[16][68];
    const int t  = threadIdx.x;
    const int bm = blockIdx.y * 64, bn = blockIdx.x * 64;
    const int lr = t >> 2, lk = (t & 3) * 4;
    const int ty = t >> 4, tx = t & 15;
    float acc[4][4] = {};

    for (int k0 = 0; k0 < K; k0 += 16) {
        int am = bm + lr;
        float4 av = make_float4(0.f, 0.f, 0.f, 0.f);
        if (am < M) av = *(const float4*)(A + (size_t)am * K + k0 + lk);
        As[lk + 0][lr] = av.x; As[lk + 1][lr] = av.y;
        As[lk + 2][lr] = av.z; As[lk + 3][lr] = av.w;
        int wn = bn + lr;
        float4 wv = make_float4(0.f, 0.f, 0.f, 0.f);
        if (wn < N) wv = *(const float4*)(W + (size_t)wn * K + k0 + lk);
        Ws[lk + 0][lr] = wv.x; Ws[lk + 1][lr] = wv.y;
        Ws[lk + 2][lr] = wv.z; Ws[lk + 3][lr] = wv.w;
        __syncthreads();
        #pragma unroll
        for (int kk = 0; kk < 16; kk++) {
            float4 a = *(const float4*)&As[kk][ty * 4];
            float4 b = *(const float4*)&Ws[kk][tx * 4];
            float av4[4] = {a.x, a.y, a.z, a.w};
            float bv4[4] = {b.x, b.y, b.z, b.w};
            #pragma unroll
            for (int i = 0; i < 4; i++)
                #pragma unroll
                for (int j = 0; j < 4; j++)
                    acc[i][j] += av4[i] * bv4[j];
        }
        __syncthreads();
    }
    #pragma unroll
    for (int i = 0; i < 4; i++) {
        int m = bm + ty * 4 + i;
        if (m >= M) continue;
        #pragma unroll
        for (int j = 0; j < 4; j++) {
            int n = bn + tx * 4 + j;
            if (n >= N) continue;
            float v = acc[i][j] + bias[n];
            if (ACT == 1) v = 0.5f * v * (1.0f + erff(v * 0.70710678118654752f));
            if (WF32) C[(size_t)m * N + n] = v;
            if (WSPLIT) splitw(v, Ch, Cl, (size_t)m * N + n);
        }
    }
}

// ---------------- fold prep (both layers via blockIdx.z) ----------------
__global__ void fold_prep_k(const float* __restrict__ vw0, const float* __restrict__ ow0,
                            const float* __restrict__ vb0, const float* __restrict__ ob0,
                            float* __restrict__ vwT0, float* __restrict__ cb0)
{
    const int lz = blockIdx.z;
    const float* vw = vw0 + (size_t)lz * Dq * Dq;
    const float* ow = ow0 + (size_t)lz * Dq * Dq;
    const float* vb = vb0 + lz * Dq;
    const float* ob = ob0 + lz * Dq;
    float* vwT = vwT0 + (size_t)lz * Dq * Dq;
    float* cb  = cb0 + lz * Dq;

    __shared__ float tile[32][33];
    const int bx = blockIdx.x, by = blockIdx.y;    // grid (16,16,L)
    const int t = threadIdx.x;
    const int tx = t & 31, ty = t >> 5;
    #pragma unroll
    for (int r = 0; r < 4; r++)
        tile[ty + r * 8][tx] = vw[(size_t)(by * 32 + ty + r * 8) * Dq + bx * 32 + tx];
    __syncthreads();
    #pragma unroll
    for (int r = 0; r < 4; r++)
        vwT[(size_t)(bx * 32 + ty + r * 8) * Dq + by * 32 + tx] = tile[tx][ty + r * 8];

    if (by == 0) {
        int n = bx * 32 + (t >> 3), ks = t & 7;
        float p = 0.f;
        for (int k = ks * 64; k < ks * 64 + 64; k++) p += ow[(size_t)n * Dq + k] * vb[k];
        p += __shfl_xor_sync(0xffffffffu, p, 1);
        p += __shfl_xor_sync(0xffffffffu, p, 2);
        p += __shfl_xor_sync(0xffffffffu, p, 4);
        if (ks == 0) cb[n] = p + ob[n];
    }
}

// ---------------- fused weight split ----------------
struct SplitSeg { const float* src; __nv_bfloat16* h; __nv_bfloat16* l; int n; };
struct SplitArgs { SplitSeg seg[14]; int total; };

__global__ void split_all_k(SplitArgs a) {
    int i = blockIdx.x * 256 + threadIdx.x;
    if (i >= a.total) return;
    int idx = i, s = 0;
    while (idx >= a.seg[s].n) { idx -= a.seg[s].n; s++; }
    splitw(a.seg[s].src[idx], a.seg[s].h, a.seg[s].l, idx);
}

// ---------------- sims + inline norms + top-k + agg(split) + states init ----------------
__global__ void sims_agg_k(const int* __restrict__ eids, const int* __restrict__ nids)
{
    int be = blockIdx.x, t = threadIdx.x;
    int lane = t & 31, w = t >> 5;
    __shared__ float se[Dq];
    __shared__ float ssim[Nq];
    __shared__ int   snid[Nq];
    __shared__ int   ssel[Kq];
    __shared__ float red[32];

    int eid = eids[be];
    float sq = 0.f;
    for (int d = t; d < Dq; d += 256) {
        float x = g_proj[eid * Dq + d];
        se[d] = x;
        g_states[(size_t)be * Dq + d] = x;
        sq += x * x;
    }
    float en = fmaxf(sqrtf(blockSum(sq, red)), 1e-12f);

    for (int n = w; n < Nq; n += 8) {
        int nid = nids[be * Nq + n];
        float s = 0.f, q = 0.f;
        for (int d = lane; d < Dq; d += 32) {
            float p = g_proj[nid * Dq + d];
            s += p * se[d];
            q += p * p;
        }
        s = warpSum(s); q = warpSum(q);
        if (lane == 0) {
            snid[n] = nid;
            ssim[n] = s / (fmaxf(sqrtf(q), 1e-12f) * en);
        }
    }
    __syncthreads();

    if (w == 0) {
        float sv = ssim[lane];
        for (int it = 0; it < Kq; it++) {
            float bs = sv; int bi = lane;
            #pragma unroll
            for (int o = 16; o; o >>= 1) {
                float os = __shfl_xor_sync(0xffffffffu, bs, o);
                int   oi = __shfl_xor_sync(0xffffffffu, bi, o);
                if (os > bs || (os == bs && oi < bi)) { bs = os; bi = oi; }
            }
            if (lane == bi) sv = -FLT_MAX;
            if (lane == 0) ssel[it] = snid[bi];
        }
    }
    __syncthreads();

    for (int d = t; d < Dq; d += 256) {
        float a = 0.f;
        #pragma unroll
        for (int k2 = 0; k2 < Kq; k2++) a += g_proj[ssel[k2] * Dq + d];
        splitw(a * (1.0f / Kq), g_agg_h, g_agg_l, (size_t)be * Dq + d);
    }
}

// ---------------- layernorm -> fp32 states + hi/lo split ----------------
template<bool MASK>
__global__ void ln_k(const float* __restrict__ in, const float* __restrict__ g,
                     const float* __restrict__ b, const float* __restrict__ mask,
                     float* __restrict__ out, __nv_bfloat16* __restrict__ oh,
                     __nv_bfloat16* __restrict__ ol)
{
    int be = blockIdx.x, t = threadIdx.x;
    __shared__ float red[32];
    const float* x = in + (size_t)be * Dq;
    float v0 = x[t], v1 = x[t + 256];
    float mu = blockSum(v0 + v1, red) * (1.0f / Dq);
    float d0 = v0 - mu, d1 = v1 - mu;
    float var = blockSum(d0 * d0 + d1 * d1, red) * (1.0f / Dq);
    float r = rsqrtf(var + EPSq);
    float mk = MASK ? mask[be] : 1.0f;
    float o0 = (d0 * r * g[t      ] + b[t      ]) * mk;
    float o1 = (d1 * r * g[t + 256] + b[t + 256]) * mk;
    size_t i0 = (size_t)be * Dq + t, i1 = i0 + 256;
    out[i0] = o0; out[i1] = o1;
    splitw(o0, oh, ol, i0);
    splitw(o1, oh, ol, i1);
}

// ---------------- pack kv bias ----------------
__global__ void pack_kvb_k(const float* __restrict__ kb, const float* __restrict__ vb) {
    int i = blockIdx.x * 256 + threadIdx.x;    // 1024
    g_kvb[i] = (i < Dq) ? kb[i] : vb[i - Dq];
}

// ---------------- no-edge flags ----------------
__global__ void noedge_k(const float* __restrict__ mask) {
    int b = blockIdx.x;
    __shared__ float red[32];
    float s = blockSum(mask[b * Eq + threadIdx.x], red);
    if (threadIdx.x == 0) g_noedge[b] = (s == 0.f) ? 0.f : 1.f;
}

// ---------------- memory-token cross attention, head-parallel ----------------
__global__ void attn_k(const float* __restrict__ mask)
{
    int bmh = blockIdx.x;                    // B*M*H = 2048
    int h = bmh & 7, bm = bmh >> 3;
    int b = bm >> 5, m = bm & 31;
    int t = threadIdx.x;
    __shared__ float qh[DHq];
    __shared__ float sc[Eq];
    __shared__ float red[32];
    __shared__ float outp[4][DHq];

    if (t < DHq) qh[t] = g_q[m * Dq + h * DHq + t];
    __syncthreads();

    const float* kr = g_kv + (size_t)(b * Eq + t) * (2 * Dq) + h * DHq;
    float dot = 0.f;
    #pragma unroll
    for (int d = 0; d < DHq; d++) dot += qh[d] * kr[d];
    float s = dot * 0.125f;
    if (mask[b * Eq + t] == 0.f) s = -FLT_MAX;

    float mx = blockMax(s, red);
    float e = expf(s - mx);
    sc[t] = e;
    float sum = blockSum(e, red);

    int d = t & 63, gp = t >> 6;
    const float* vb0 = g_kv + (size_t)(b * Eq) * (2 * Dq) + Dq + h * DHq + d;
    float acc = 0.f;
    #pragma unroll 4
    for (int e2 = gp * 64; e2 < gp * 64 + 64; e2++)
        acc += sc[e2] * vb0[(size_t)e2 * (2 * Dq)];
    outp[gp][d] = acc;
    __syncthreads();
    if (t < DHq) {
        float o = (outp[0][t] + outp[1][t] + outp[2][t] + outp[3][t]) / sum;
        splitw(o, g_mem_h, g_mem_l, (size_t)bm * Dq + h * DHq + t);
    }
}

// ---------------- no-edge mask + split for final proj ----------------
__global__ void memmask_k() {
    int i = blockIdx.x * 256 + threadIdx.x;
    int b = i / (Mq * Dq);
    splitw(g_mem2[i] * g_noedge[b], g_m2_h, g_m2_l, i);
}

// ---------------- launch ----------------
extern "C" void kernel_launch(void* const* d_in, const int* in_sizes, int n_in,
                              void* d_out, int out_size)
{
    const int*   edge_ids  = (const int*)  d_in[0];
    const int*   neigh_ids = (const int*)  d_in[1];
    const float* edge_mask = (const float*)d_in[2];
    const float* rel_emb   = (const float*)d_in[3];
    const float* rp_w      = (const float*)d_in[4];
    const float* rp_b      = (const float*)d_in[5];
    const float* ly_vw     = (const float*)d_in[6];
    const float* ly_vb     = (const float*)d_in[7];
    const float* ly_ow     = (const float*)d_in[8];
    const float* ly_ob     = (const float*)d_in[9];
    const float* ly_n1g    = (const float*)d_in[10];
    const float* ly_n1b    = (const float*)d_in[11];
    const float* ly_n2g    = (const float*)d_in[12];
    const float* ly_n2b    = (const float*)d_in[13];
    const float* ly_w1     = (const float*)d_in[14];
    const float* ly_b1     = (const float*)d_in[15];
    const float* ly_w2     = (const float*)d_in[16];
    const float* ly_b2     = (const float*)d_in[17];
    const float* mem_q     = (const float*)d_in[18];
    const float* t_qw      = (const float*)d_in[19];
    const float* t_qb      = (const float*)d_in[20];
    const float* t_kw      = (const float*)d_in[21];
    const float* t_kb      = (const float*)d_in[22];
    const float* t_vw      = (const float*)d_in[23];
    const float* t_vb      = (const float*)d_in[24];
    const float* t_ow      = (const float*)d_in[25];
    const float* t_ob      = (const float*)d_in[26];
    const float* proj_w    = (const float*)d_in[27];
    const float* proj_b    = (const float*)d_in[28];
    float* out = (float*)d_out;

    float *p_proj, *p_states, *p_t2, *p_kv, *p_kvb, *p_q, *p_mem2, *p_vwT, *p_cb, *p_zero;
    cudaGetSymbolAddress((void**)&p_proj,   g_proj);
    cudaGetSymbolAddress((void**)&p_states, g_states);
    cudaGetSymbolAddress((void**)&p_t2,     g_t2);
    cudaGetSymbolAddress((void**)&p_kv,     g_kv);
    cudaGetSymbolAddress((void**)&p_kvb,    g_kvb);
    cudaGetSymbolAddress((void**)&p_q,      g_q);
    cudaGetSymbolAddress((void**)&p_mem2,   g_mem2);
    cudaGetSymbolAddress((void**)&p_vwT,    g_vwT);
    cudaGetSymbolAddress((void**)&p_cb,     g_cb);
    cudaGetSymbolAddress((void**)&p_zero,   g_zero512);

    __nv_bfloat16 *p_agg_h, *p_agg_l, *p_st_h, *p_st_l, *p_hid_h, *p_hid_l;
    __nv_bfloat16 *p_mem_h, *p_mem_l, *p_m2_h, *p_m2_l;
    cudaGetSymbolAddress((void**)&p_agg_h,  g_agg_h);
    cudaGetSymbolAddress((void**)&p_agg_l,  g_agg_l);
    cudaGetSymbolAddress((void**)&p_st_h,   g_st_h);
    cudaGetSymbolAddress((void**)&p_st_l,   g_st_l);
    cudaGetSymbolAddress((void**)&p_hid_h,  g_hid_h);
    cudaGetSymbolAddress((void**)&p_hid_l,  g_hid_l);
    cudaGetSymbolAddress((void**)&p_mem_h,  g_mem_h);
    cudaGetSymbolAddress((void**)&p_mem_l,  g_mem_l);
    cudaGetSymbolAddress((void**)&p_m2_h,   g_m2_h);
    cudaGetSymbolAddress((void**)&p_m2_l,   g_m2_l);

    __nv_bfloat16 *p_emb_h, *p_emb_l, *p_rpw_h, *p_rpw_l, *p_ow_h, *p_ow_l, *p_vwT_h, *p_vwT_l;
    __nv_bfloat16 *p_wc_h, *p_wc_l, *p_w1_h, *p_w1_l, *p_w2_h, *p_w2_l;
    __nv_bfloat16 *p_kvw_h, *p_kvw_l, *p_to_h, *p_to_l, *p_pw_h, *p_pw_l;
    cudaGetSymbolAddress((void**)&p_emb_h, g_emb_h);
    cudaGetSymbolAddress((void**)&p_emb_l, g_emb_l);
    cudaGetSymbolAddress((void**)&p_rpw_h, g_rpw_h);
    cudaGetSymbolAddress((void**)&p_rpw_l, g_rpw_l);
    cudaGetSymbolAddress((void**)&p_ow_h,  g_ow_h);
    cudaGetSymbolAddress((void**)&p_ow_l,  g_ow_l);
    cudaGetSymbolAddress((void**)&p_vwT_h, g_vwT_h);
    cudaGetSymbolAddress((void**)&p_vwT_l, g_vwT_l);
    cudaGetSymbolAddress((void**)&p_wc_h,  g_wc_h);
    cudaGetSymbolAddress((void**)&p_wc_l,  g_wc_l);
    cudaGetSymbolAddress((void**)&p_w1_h,  g_w1_h);
    cudaGetSymbolAddress((void**)&p_w1_l,  g_w1_l);
    cudaGetSymbolAddress((void**)&p_w2_h,  g_w2_h);
    cudaGetSymbolAddress((void**)&p_w2_l,  g_w2_l);
    cudaGetSymbolAddress((void**)&p_kvw_h, g_kvw_h);
    cudaGetSymbolAddress((void**)&p_kvw_l, g_kvw_l);
    cudaGetSymbolAddress((void**)&p_to_h,  g_to_h);
    cudaGetSymbolAddress((void**)&p_to_l,  g_to_l);
    cudaGetSymbolAddress((void**)&p_pw_h,  g_pw_h);
    cudaGetSymbolAddress((void**)&p_pw_l,  g_pw_l);

    constexpr int DD = Dq * Dq, DD4 = 4 * Dq * Dq;

    // TN=64 shapes: 512 threads (4x4 warps) — best measured on grid<=256 latency-bound GEMMs.
    // TN=128 (kC): 256 threads (2x4) — R6-proven best mma:ldsm ratio.
    auto kA = mma_nt<128,64,4,4,512, 0,false,false,true>;   // split out (Wc, z-batched)
    auto kB = mma_nt<128,64,4,4,512, 0,true ,true ,false>;  // res + f32 out
    auto kC = mma_nt<128,128,2,4,256, 1,false,false,true>;  // gelu + split out
    auto kD = mma_nt<128,64,4,4,512, 0,false,true ,false>;  // f32 out
    constexpr int SM64  = (128 + 64)  * PADK * 2 * NSTG;  // 110,592
    constexpr int SM128 = (128 + 128) * PADK * 2 * NSTG;  // 147,456
    cudaFuncSetAttribute(kA, cudaFuncAttributeMaxDynamicSharedMemorySize, SM64);
    cudaFuncSetAttribute(kB, cudaFuncAttributeMaxDynamicSharedMemorySize, SM64);
    cudaFuncSetAttribute(kC, cudaFuncAttributeMaxDynamicSharedMemorySize, SM128);
    cudaFuncSetAttribute(kD, cudaFuncAttributeMaxDynamicSharedMemorySize, SM64);

    // (1) fold prep both layers
    fold_prep_k<<<dim3(16,16,Lq), 256>>>(ly_vw, ly_ow, ly_vb, ly_ob, p_vwT, p_cb);

    // (2) fused splits (14 segments; g_emb pad rows stay zero from static init)
    {
        SplitArgs sa;
        int s = 0, tot = 0;
        auto add = [&](const float* src, __nv_bfloat16* h, __nv_bfloat16* l, int n) {
            sa.seg[s++] = SplitSeg{src, h, l, n}; tot += n;
        };
        for (int l = 0; l < Lq; l++) {
            add(ly_w1 + (size_t)l * DD4, p_w1_h + (size_t)l * DD4, p_w1_l + (size_t)l * DD4, DD4);
            add(ly_w2 + (size_t)l * DD4, p_w2_h + (size_t)l * DD4, p_w2_l + (size_t)l * DD4, DD4);
            add(ly_ow + (size_t)l * DD,  p_ow_h + (size_t)l * DD,  p_ow_l + (size_t)l * DD,  DD);
            add(p_vwT + (size_t)l * DD,  p_vwT_h + (size_t)l * DD, p_vwT_l + (size_t)l * DD, DD);
        }
        add(t_kw,    p_kvw_h,      p_kvw_l,      DD);
        add(t_vw,    p_kvw_h + DD, p_kvw_l + DD, DD);
        add(t_ow,    p_to_h,       p_to_l,       DD);
        add(proj_w,  p_pw_h,       p_pw_l,       HLLMq * Dq);
        add(rel_emb, p_emb_h,      p_emb_l,      Rq * RDq);
        add(rp_w,    p_rpw_h,      p_rpw_l,      Dq * RDq);
        sa.total = tot;
        split_all_k<<<(tot + 255) / 256, 256>>>(sa);
    }

    // (3) q-proj (tiny fp32)
    gemm_nt<0,true,false><<<dim3(Dq/64, 1), 256>>>(mem_q, t_qw, t_qb, p_q, nullptr, nullptr,
                                                   Mq, Dq, Dq);

    // (4) relation projection (bf16x3) — ncu profile slot
    kD<<<dim3(Dq/64, RPAD/128), 512, SM64>>>(
        p_emb_h, p_emb_l, p_rpw_h, p_rpw_l, rp_b, nullptr, p_proj, nullptr, nullptr,
        RPAD, Dq, RDq);

    // (5) Wc = ow @ vw (bf16x3), both layers in one launch (z = layer; weights are
    //     contiguous per layer so A/B/C base pointers + z*TM row offset line up:
    //     grid.y = Dq/128 covers one layer's 512 rows, z advances by Dq rows = l*DD elems)
    kA<<<dim3(Dq/64, Dq/128, Lq), 512, SM64>>>(
        p_ow_h, p_ow_l, p_vwT_h, p_vwT_l,
        p_zero, nullptr, nullptr, p_wc_h, p_wc_l, Lq*Dq, Dq, Dq);
    // NOTE: B operand (vwT) must also advance per layer — handled by passing M=Lq*Dq and
    // bm spanning both layers ONLY for A and C. B differs per layer, so fall back:
    // (the kernel uses the same Bh/Bl for all z). To keep correctness, launch per layer when
    // B differs. Revert to per-layer launches:
    for (int l = 0; l < Lq; l++)
        kA<<<dim3(Dq/64, Dq/128), 512, SM64>>>(
            p_ow_h + (size_t)l*DD, p_ow_l + (size_t)l*DD,
            p_vwT_h + (size_t)l*DD, p_vwT_l + (size_t)l*DD,
            p_zero, nullptr, nullptr, p_wc_h + (size_t)l*DD, p_wc_l + (size_t)l*DD, Dq, Dq, Dq);

    // misc prep
    pack_kvb_k<<<4, 256>>>(t_kb, t_vb);
    noedge_k<<<Bq, 256>>>(edge_mask);

    // sims + top-k + agg + states init
    sims_agg_k<<<BEq, 256>>>(edge_ids, neigh_ids);

    // relation-context layers
    for (int l = 0; l < Lq; l++) {
        kB<<<dim3(Dq/64, BEq/128), 512, SM64>>>(
            p_agg_h, p_agg_l, p_wc_h + (size_t)l*DD, p_wc_l + (size_t)l*DD,
            p_cb + l*Dq, p_states, p_t2, nullptr, nullptr, BEq, Dq, Dq);
        ln_k<false><<<BEq, 256>>>(p_t2, ly_n1g + l*Dq, ly_n1b + l*Dq, nullptr,
                                  p_states, p_st_h, p_st_l);

        kC<<<dim3(4*Dq/128, BEq/128), 256, SM128>>>(
            p_st_h, p_st_l, p_w1_h + (size_t)l*DD4, p_w1_l + (size_t)l*DD4,
            ly_b1 + l*4*Dq, nullptr, nullptr, p_hid_h, p_hid_l, BEq, 4*Dq, Dq);

        kB<<<dim3(Dq/64, BEq/128), 512, SM64>>>(
            p_hid_h, p_hid_l, p_w2_h + (size_t)l*DD4, p_w2_l + (size_t)l*DD4,
            ly_b2 + l*Dq, p_states, p_t2, nullptr, nullptr, BEq, Dq, 4*Dq);
        ln_k<true><<<BEq, 256>>>(p_t2, ly_n2g + l*Dq, ly_n2b + l*Dq, edge_mask,
                                 p_states, p_st_h, p_st_l);
    }

    // tokenizer K|V projection (combined)
    kD<<<dim3(2*Dq/64, BEq/128), 512, SM64>>>(
        p_st_h, p_st_l, p_kvw_h, p_kvw_l, p_kvb, nullptr, p_kv, nullptr, nullptr, BEq, 2*Dq, Dq);

    // attention + output proj + masking
    attn_k<<<Bq * Mq * Hq, 256>>>(edge_mask);
    kD<<<dim3(Dq/64, (Bq*Mq)/128), 512, SM64>>>(
        p_mem_h, p_mem_l, p_to_h, p_to_l, t_ob, nullptr, p_mem2, nullptr, nullptr, Bq*Mq, Dq, Dq);
    memmask_k<<<(Bq*Mq*Dq)/256, 256>>>();

    // LLM projection -> d_out
    kD<<<dim3(HLLMq/64, (Bq*Mq)/128), 512, SM64>>>(
        p_m2_h, p_m2_l, p_pw_h, p_pw_l, proj_b, nullptr, out, nullptr, nullptr, Bq*Mq, HLLMq, Dq);
}

// round 11
// speedup vs baseline: 1.5747x; 1.1435x over previous
#include <cuda_runtime.h>
#include <cuda_bf16.h>
#include <math.h>
#include <float.h>
#include <stdint.h>

// ---------------- problem constants ----------------
constexpr int Bq = 8, Eq = 256, Nq = 32;
constexpr int Dq = 512, RDq = 768, Rq = 2000;
constexpr int Lq = 2, Kq = 8, Mq = 32, Hq = 8, DHq = 64;
constexpr int HLLMq = 4096;
constexpr int BEq = Bq * Eq;          // 2048 edge tokens
constexpr int RPAD = 2048;            // rel rows padded to TM multiple
constexpr float EPSq = 1e-5f;

// ---------------- scratch (device globals; no allocs allowed) ----------------
__device__ float g_proj  [RPAD * Dq];
__device__ float g_states[BEq * Dq];
__device__ float g_t2    [BEq * Dq];
__device__ float g_kv    [BEq * 2 * Dq];
__device__ float g_kvb   [2 * Dq];
__device__ float g_q     [Mq * Dq];
__device__ float g_mem2  [Bq * Mq * Dq];
__device__ float g_noedge[Bq];
__device__ float g_vwT   [Lq][Dq * Dq];
__device__ float g_cb    [Lq][Dq];
__device__ float g_zero512[Dq];
// bf16 hi/lo split activation buffers
__device__ __align__(256) __nv_bfloat16 g_agg_h[BEq * Dq],      g_agg_l[BEq * Dq];
__device__ __align__(256) __nv_bfloat16 g_st_h [BEq * Dq],      g_st_l [BEq * Dq];
__device__ __align__(256) __nv_bfloat16 g_hid_h[BEq * 4 * Dq],  g_hid_l[BEq * 4 * Dq];
__device__ __align__(256) __nv_bfloat16 g_mem_h[Bq * Mq * Dq],  g_mem_l[Bq * Mq * Dq];
__device__ __align__(256) __nv_bfloat16 g_m2_h [Bq * Mq * Dq],  g_m2_l [Bq * Mq * Dq];
// bf16 hi/lo split weight buffers
__device__ __align__(256) __nv_bfloat16 g_emb_h[RPAD * RDq],     g_emb_l[RPAD * RDq];
__device__ __align__(256) __nv_bfloat16 g_rpw_h[Dq * RDq],       g_rpw_l[Dq * RDq];
__device__ __align__(256) __nv_bfloat16 g_ow_h[Lq][Dq * Dq],     g_ow_l[Lq][Dq * Dq];
__device__ __align__(256) __nv_bfloat16 g_vwT_h[Lq][Dq * Dq],    g_vwT_l[Lq][Dq * Dq];
__device__ __align__(256) __nv_bfloat16 g_wc_h[Lq][Dq * Dq],     g_wc_l[Lq][Dq * Dq];
__device__ __align__(256) __nv_bfloat16 g_w1_h[Lq][4 * Dq * Dq], g_w1_l[Lq][4 * Dq * Dq];
__device__ __align__(256) __nv_bfloat16 g_w2_h[Lq][4 * Dq * Dq], g_w2_l[Lq][4 * Dq * Dq];
__device__ __align__(256) __nv_bfloat16 g_kvw_h[2 * Dq * Dq],    g_kvw_l[2 * Dq * Dq];
__device__ __align__(256) __nv_bfloat16 g_to_h[Dq * Dq],         g_to_l[Dq * Dq];
__device__ __align__(256) __nv_bfloat16 g_pw_h[HLLMq * Dq],      g_pw_l[HLLMq * Dq];

__device__ __forceinline__ void splitw(float v, __nv_bfloat16* H, __nv_bfloat16* L, size_t i) {
    __nv_bfloat16 h = __float2bfloat16(v);
    H[i] = h;
    L[i] = __float2bfloat16(v - __bfloat162float(h));
}

__device__ __forceinline__ uint32_t smem_u32(const void* p) {
    uint32_t a;
    asm("{ .reg .u64 t; cvta.to.shared.u64 t, %1; cvt.u32.u64 %0, t; }" : "=r"(a) : "l"(p));
    return a;
}

// ---------------- reductions ----------------
__device__ __forceinline__ float warpSum(float v) {
    #pragma unroll
    for (int o = 16; o; o >>= 1) v += __shfl_xor_sync(0xffffffffu, v, o);
    return v;
}
__device__ __forceinline__ float warpMax(float v) {
    #pragma unroll
    for (int o = 16; o; o >>= 1) v = fmaxf(v, __shfl_xor_sync(0xffffffffu, v, o));
    return v;
}
__device__ __forceinline__ float blockSum(float v, float* red) {
    int lane = threadIdx.x & 31, w = threadIdx.x >> 5;
    int nw = blockDim.x >> 5;
    v = warpSum(v);
    if (lane == 0) red[w] = v;
    __syncthreads();
    if (w == 0) {
        float r = (lane < nw) ? red[lane] : 0.f;
        r = warpSum(r);
        if (lane == 0) red[0] = r;
    }
    __syncthreads();
    float out = red[0];
    __syncthreads();
    return out;
}
__device__ __forceinline__ float blockMax(float v, float* red) {
    int lane = threadIdx.x & 31, w = threadIdx.x >> 5;
    int nw = blockDim.x >> 5;
    v = warpMax(v);
    if (lane == 0) red[w] = v;
    __syncthreads();
    if (w == 0) {
        float r = (lane < nw) ? red[lane] : -FLT_MAX;
        r = warpMax(r);
        if (lane == 0) red[0] = r;
    }
    __syncthreads();
    float out = red[0];
    __syncthreads();
    return out;
}

// ---------------- mma.sync primitives ----------------
__device__ __forceinline__ void mma16816(float* d, const uint32_t* a, const uint32_t* b) {
    asm volatile("mma.sync.aligned.m16n8k16.row.col.f32.bf16.bf16.f32 "
        "{%0,%1,%2,%3}, {%4,%5,%6,%7}, {%8,%9}, {%0,%1,%2,%3};"
        : "+f"(d[0]), "+f"(d[1]), "+f"(d[2]), "+f"(d[3])
        : "r"(a[0]), "r"(a[1]), "r"(a[2]), "r"(a[3]), "r"(b[0]), "r"(b[1]));
}
__device__ __forceinline__ void ldsm4(uint32_t& r0, uint32_t& r1, uint32_t& r2, uint32_t& r3,
                                      uint32_t addr) {
    asm volatile("ldmatrix.sync.aligned.m8n8.x4.shared.b16 {%0,%1,%2,%3}, [%4];"
        : "=r"(r0), "=r"(r1), "=r"(r2), "=r"(r3) : "r"(addr));
}
__device__ __forceinline__ void cpasync16(uint32_t dst, const void* src) {
    asm volatile("cp.async.cg.shared.global [%0], [%1], 16;\n" :: "r"(dst), "l"(src) : "memory");
}

// ================= bf16x3 NT GEMM via mma.sync, BK=64, 4-stage pipeline =================
// Simple R6 inner loop. NTHR/warp-shape are template params.
constexpr int PADK = 72;
constexpr int NSTG = 4;

template<int TM, int TN, int WR, int WC, int NTHR, int ACT, bool RES, bool WF32, bool WSPLIT>
__global__ __launch_bounds__(NTHR)
void mma_nt(const __nv_bfloat16* __restrict__ Ah, const __nv_bfloat16* __restrict__ Al,
            const __nv_bfloat16* __restrict__ Bh, const __nv_bfloat16* __restrict__ Bl,
            const float* __restrict__ bias, const float* __restrict__ res,
            float* __restrict__ Cf, __nv_bfloat16* __restrict__ Ch, __nv_bfloat16* __restrict__ Cl,
            int M, int N, int K)
{
    static_assert(WR * WC == NTHR / 32, "warp grid must cover block");
    extern __shared__ __align__(128) __nv_bfloat16 smem[];
    constexpr int STG_E = (TM + TN) * PADK;
    constexpr int tm = TM / WR, tn = TN / WC;
    constexpr int MT = tm / 16, NT = tn / 8;

    const int tid = threadIdx.x;
    const int wid = tid >> 5, lane = tid & 31;
    const int bm = blockIdx.y * TM, bn = blockIdx.x * TN;
    const int wm = (wid / WC) * tm, wn = (wid % WC) * tn;
    const uint32_t sbase = smem_u32(smem);

    const int NI = (3 * K) / 64;

    auto load_stage = [&](int stage, int buf) {
        int c0 = stage * 64;
        int term = c0 / K;
        int kk = c0 - term * K;
        const __nv_bfloat16* As = (term < 2) ? Ah : Al;
        const __nv_bfloat16* Bs = (term == 1) ? Bl : Bh;
        uint32_t base = sbase + (uint32_t)buf * STG_E * 2;
        constexpr int CHA = TM * 8, CH = (TM + TN) * 8;
        #pragma unroll
        for (int j = 0; j < CH / NTHR; ++j) {
            int f = tid + NTHR * j;
            if (f < CHA) {
                int row = f >> 3, ch = f & 7;
                cpasync16(base + (uint32_t)(row * PADK + ch * 8) * 2,
                          As + (size_t)(bm + row) * K + kk + ch * 8);
            } else {
                int f2 = f - CHA;
                int row = f2 >> 3, ch = f2 & 7;
                cpasync16(base + (uint32_t)(TM * PADK + row * PADK + ch * 8) * 2,
                          Bs + (size_t)(bn + row) * K + kk + ch * 8);
            }
        }
        asm volatile("cp.async.commit_group;\n" ::: "memory");
    };

    float d[MT][NT][4];
    #pragma unroll
    for (int a = 0; a < MT; a++)
        #pragma unroll
        for (int b = 0; b < NT; b++)
            #pragma unroll
            for (int c = 0; c < 4; c++) d[a][b][c] = 0.f;

    load_stage(0, 0);
    load_stage(1, 1);
    load_stage(2, 2);

    const int a_lrow = lane & 15, a_lk = (lane >> 4) * 8;
    const int bq = lane >> 3;
    const int b_lrow = (lane & 7) + ((bq >> 1) * 8);
    const int b_lk = (bq & 1) * 8;

    for (int i = 0; i < NI; ++i) {
        if (i + 3 <= NI)      asm volatile("cp.async.wait_group 2;\n" ::: "memory");
        else if (i + 2 == NI) asm volatile("cp.async.wait_group 1;\n" ::: "memory");
        else                  asm volatile("cp.async.wait_group 0;\n" ::: "memory");
        __syncthreads();

        if (i + 3 < NI) load_stage(i + 3, (i + 3) & (NSTG - 1));

        const uint32_t abase = sbase + (uint32_t)(i & (NSTG - 1)) * STG_E * 2;
        const uint32_t bbase = abase + TM * PADK * 2;

        #pragma unroll
        for (int kh = 0; kh < 4; ++kh) {
            const int kc = kh * 16;
            uint32_t afr[MT][4];
            #pragma unroll
            for (int mt = 0; mt < MT; ++mt)
                ldsm4(afr[mt][0], afr[mt][1], afr[mt][2], afr[mt][3],
                      abase + (uint32_t)((wm + mt * 16 + a_lrow) * PADK + kc + a_lk) * 2);
            uint32_t bfr[NT][2];
            #pragma unroll
            for (int nt2 = 0; nt2 < NT / 2; ++nt2) {
                uint32_t r0, r1, r2, r3;
                ldsm4(r0, r1, r2, r3,
                      bbase + (uint32_t)((wn + nt2 * 16 + b_lrow) * PADK + kc + b_lk) * 2);
                bfr[nt2 * 2][0] = r0; bfr[nt2 * 2][1] = r1;
                bfr[nt2 * 2 + 1][0] = r2; bfr[nt2 * 2 + 1][1] = r3;
            }
            #pragma unroll
            for (int mt = 0; mt < MT; ++mt)
                #pragma unroll
                for (int nt = 0; nt < NT; ++nt)
                    mma16816(d[mt][nt], afr[mt], bfr[nt]);
        }
    }

    const int erow = lane >> 2, ecol = (lane & 3) * 2;
    #pragma unroll
    for (int mt = 0; mt < MT; ++mt) {
        #pragma unroll
        for (int h = 0; h < 2; ++h) {
            const int row = bm + wm + mt * 16 + erow + h * 8;
            #pragma unroll
            for (int nt = 0; nt < NT; ++nt) {
                const int n = bn + wn + nt * 8 + ecol;
                float v0 = d[mt][nt][h * 2 + 0];
                float v1 = d[mt][nt][h * 2 + 1];
                float2 bv = *(const float2*)(bias + n);
                v0 += bv.x; v1 += bv.y;
                if (RES) {
                    float2 rv = *(const float2*)(res + (size_t)row * N + n);
                    v0 += rv.x; v1 += rv.y;
                }
                if (ACT == 1) {
                    v0 = 0.5f * v0 * (1.0f + erff(v0 * 0.70710678118654752f));
                    v1 = 0.5f * v1 * (1.0f + erff(v1 * 0.70710678118654752f));
                }
                if (WF32)
                    *(float2*)(Cf + (size_t)row * N + n) = make_float2(v0, v1);
                if (WSPLIT) {
                    __nv_bfloat16 h0 = __float2bfloat16(v0), h1 = __float2bfloat16(v1);
                    __nv_bfloat16 l0 = __float2bfloat16(v0 - __bfloat162float(h0));
                    __nv_bfloat16 l1 = __float2bfloat16(v1 - __bfloat162float(h1));
                    uint32_t hp = ((uint32_t)__bfloat16_as_ushort(h1) << 16) | __bfloat16_as_ushort(h0);
                    uint32_t lp = ((uint32_t)__bfloat16_as_ushort(l1) << 16) | __bfloat16_as_ushort(l0);
                    *(uint32_t*)(Ch + (size_t)row * N + n) = hp;
                    *(uint32_t*)(Cl + (size_t)row * N + n) = lp;
                }
            }
        }
    }
}

// ---------------- fp32 SIMT NT GEMM (q-proj only) ----------------
template<int ACT, bool WF32, bool WSPLIT>
__global__ void gemm_nt(const float* __restrict__ A, const float* __restrict__ W,
                        const float* __restrict__ bias,
                        float* __restrict__ C, __nv_bfloat16* __restrict__ Ch,
                        __nv_bfloat16* __restrict__ Cl, int M, int N, int K)
{
    __shared__ float As[16][68];
    __shared__ float Ws[16][68];
    const int t  = threadIdx.x;
    const int bm = blockIdx.y * 64, bn = blockIdx.x * 64;
    const int lr = t >> 2, lk = (t & 3) * 4;
    const int ty = t >> 4, tx = t & 15;
    float acc[4][4] = {};

    for (int k0 = 0; k0 < K; k0 += 16) {
        int am = bm + lr;
        float4 av = make_float4(0.f, 0.f, 0.f, 0.f);
        if (am < M) av = *(const float4*)(A + (size_t)am * K + k0 + lk);
        As[lk + 0][lr] = av.x; As[lk + 1][lr] = av.y;
        As[lk + 2][lr] = av.z; As[lk + 3][lr] = av.w;
        int wn = bn + lr;
        float4 wv = make_float4(0.f, 0.f, 0.f, 0.f);
        if (wn < N) wv = *(const float4*)(W + (size_t)wn * K + k0 + lk);
        Ws[lk + 0][lr] = wv.x; Ws[lk + 1][lr] = wv.y;
        Ws[lk + 2][lr] = wv.z; Ws[lk + 3][lr] = wv.w;
        __syncthreads();
        #pragma unroll
        for (int kk = 0; kk < 16; kk++) {
            float4 a = *(const float4*)&As[kk][ty * 4];
            float4 b = *(const float4*)&Ws[kk][tx * 4];
            float av4[4] = {a.x, a.y, a.z, a.w};
            float bv4[4] = {b.x, b.y, b.z, b.w};
            #pragma unroll
            for (int i = 0; i < 4; i++)
                #pragma unroll
                for (int j = 0; j < 4; j++)
                    acc[i][j] += av4[i] * bv4[j];
        }
        __syncthreads();
    }
    #pragma unroll
    for (int i = 0; i < 4; i++) {
        int m = bm + ty * 4 + i;
        if (m >= M) continue;
        #pragma unroll
        for (int j = 0; j < 4; j++) {
            int n = bn + tx * 4 + j;
            if (n >= N) continue;
            float v = acc[i][j] + bias[n];
            if (ACT == 1) v = 0.5f * v * (1.0f + erff(v * 0.70710678118654752f));
            if (WF32) C[(size_t)m * N + n] = v;
            if (WSPLIT) splitw(v, Ch, Cl, (size_t)m * N + n);
        }
    }
}

// ---------------- fold prep (both layers via blockIdx.z) ----------------
__global__ void fold_prep_k(const float* __restrict__ vw0, const float* __restrict__ ow0,
                            const float* __restrict__ vb0, const float* __restrict__ ob0,
                            float* __restrict__ vwT0, float* __restrict__ cb0)
{
    const int lz = blockIdx.z;
    const float* vw = vw0 + (size_t)lz * Dq * Dq;
    const float* ow = ow0 + (size_t)lz * Dq * Dq;
    const float* vb = vb0 + lz * Dq;
    const float* ob = ob0 + lz * Dq;
    float* vwT = vwT0 + (size_t)lz * Dq * Dq;
    float* cb  = cb0 + lz * Dq;

    __shared__ float tile[32][33];
    const int bx = blockIdx.x, by = blockIdx.y;
    const int t = threadIdx.x;
    const int tx = t & 31, ty = t >> 5;
    #pragma unroll
    for (int r = 0; r < 4; r++)
        tile[ty + r * 8][tx] = vw[(size_t)(by * 32 + ty + r * 8) * Dq + bx * 32 + tx];
    __syncthreads();
    #pragma unroll
    for (int r = 0; r < 4; r++)
        vwT[(size_t)(bx * 32 + ty + r * 8) * Dq + by * 32 + tx] = tile[tx][ty + r * 8];

    if (by == 0) {
        int n = bx * 32 + (t >> 3), ks = t & 7;
        float p = 0.f;
        for (int k = ks * 64; k < ks * 64 + 64; k++) p += ow[(size_t)n * Dq + k] * vb[k];
        p += __shfl_xor_sync(0xffffffffu, p, 1);
        p += __shfl_xor_sync(0xffffffffu, p, 2);
        p += __shfl_xor_sync(0xffffffffu, p, 4);
        if (ks == 0) cb[n] = p + ob[n];
    }
}

// ---------------- fused weight split ----------------
struct SplitSeg { const float* src; __nv_bfloat16* h; __nv_bfloat16* l; int n; };
struct SplitArgs { SplitSeg seg[12]; int total; };

__global__ void split_all_k(SplitArgs a) {
    int i = blockIdx.x * 256 + threadIdx.x;
    if (i >= a.total) return;
    int idx = i, s = 0;
    while (idx >= a.seg[s].n) { idx -= a.seg[s].n; s++; }
    splitw(a.seg[s].src[idx], a.seg[s].h, a.seg[s].l, idx);
}

// ---------------- sims + inline norms + top-k + agg(split) + states init ----------------
__global__ void sims_agg_k(const int* __restrict__ eids, const int* __restrict__ nids)
{
    int be = blockIdx.x, t = threadIdx.x;
    int lane = t & 31, w = t >> 5;
    __shared__ float se[Dq];
    __shared__ float ssim[Nq];
    __shared__ int   snid[Nq];
    __shared__ int   ssel[Kq];
    __shared__ float red[32];

    int eid = eids[be];
    float sq = 0.f;
    for (int d = t; d < Dq; d += 256) {
        float x = g_proj[eid * Dq + d];
        se[d] = x;
        g_states[(size_t)be * Dq + d] = x;
        sq += x * x;
    }
    float en = fmaxf(sqrtf(blockSum(sq, red)), 1e-12f);

    for (int n = w; n < Nq; n += 8) {
        int nid = nids[be * Nq + n];
        float s = 0.f, q = 0.f;
        for (int d = lane; d < Dq; d += 32) {
            float p = g_proj[nid * Dq + d];
            s += p * se[d];
            q += p * p;
        }
        s = warpSum(s); q = warpSum(q);
        if (lane == 0) {
            snid[n] = nid;
            ssim[n] = s / (fmaxf(sqrtf(q), 1e-12f) * en);
        }
    }
    __syncthreads();

    if (w == 0) {
        float sv = ssim[lane];
        for (int it = 0; it < Kq; it++) {
            float bs = sv; int bi = lane;
            #pragma unroll
            for (int o = 16; o; o >>= 1) {
                float os = __shfl_xor_sync(0xffffffffu, bs, o);
                int   oi = __shfl_xor_sync(0xffffffffu, bi, o);
                if (os > bs || (os == bs && oi < bi)) { bs = os; bi = oi; }
            }
            if (lane == bi) sv = -FLT_MAX;
            if (lane == 0) ssel[it] = snid[bi];
        }
    }
    __syncthreads();

    for (int d = t; d < Dq; d += 256) {
        float a = 0.f;
        #pragma unroll
        for (int k2 = 0; k2 < Kq; k2++) a += g_proj[ssel[k2] * Dq + d];
        splitw(a * (1.0f / Kq), g_agg_h, g_agg_l, (size_t)be * Dq + d);
    }
}

// ---------------- layernorm -> fp32 states + hi/lo split ----------------
template<bool MASK>
__global__ void ln_k(const float* __restrict__ in, const float* __restrict__ g,
                     const float* __restrict__ b, const float* __restrict__ mask,
                     float* __restrict__ out, __nv_bfloat16* __restrict__ oh,
                     __nv_bfloat16* __restrict__ ol)
{
    int be = blockIdx.x, t = threadIdx.x;
    __shared__ float red[32];
    const float* x = in + (size_t)be * Dq;
    float v0 = x[t], v1 = x[t + 256];
    float mu = blockSum(v0 + v1, red) * (1.0f / Dq);
    float d0 = v0 - mu, d1 = v1 - mu;
    float var = blockSum(d0 * d0 + d1 * d1, red) * (1.0f / Dq);
    float r = rsqrtf(var + EPSq);
    float mk = MASK ? mask[be] : 1.0f;
    float o0 = (d0 * r * g[t      ] + b[t      ]) * mk;
    float o1 = (d1 * r * g[t + 256] + b[t + 256]) * mk;
    size_t i0 = (size_t)be * Dq + t, i1 = i0 + 256;
    out[i0] = o0; out[i1] = o1;
    splitw(o0, oh, ol, i0);
    splitw(o1, oh, ol, i1);
}

// ---------------- pack kv bias ----------------
__global__ void pack_kvb_k(const float* __restrict__ kb, const float* __restrict__ vb) {
    int i = blockIdx.x * 256 + threadIdx.x;
    g_kvb[i] = (i < Dq) ? kb[i] : vb[i - Dq];
}

// ---------------- no-edge flags ----------------
__global__ void noedge_k(const float* __restrict__ mask) {
    int b = blockIdx.x;
    __shared__ float red[32];
    float s = blockSum(mask[b * Eq + threadIdx.x], red);
    if (threadIdx.x == 0) g_noedge[b] = (s == 0.f) ? 0.f : 1.f;
}

// ---------------- memory-token cross attention, head-parallel ----------------
__global__ void attn_k(const float* __restrict__ mask)
{
    int bmh = blockIdx.x;
    int h = bmh & 7, bm = bmh >> 3;
    int b = bm >> 5, m = bm & 31;
    int t = threadIdx.x;
    __shared__ float qh[DHq];
    __shared__ float sc[Eq];
    __shared__ float red[32];
    __shared__ float outp[4][DHq];

    if (t < DHq) qh[t] = g_q[m * Dq + h * DHq + t];
    __syncthreads();

    const float* kr = g_kv + (size_t)(b * Eq + t) * (2 * Dq) + h * DHq;
    float dot = 0.f;
    #pragma unroll
    for (int d = 0; d < DHq; d++) dot += qh[d] * kr[d];
    float s = dot * 0.125f;
    if (mask[b * Eq + t] == 0.f) s = -FLT_MAX;

    float mx = blockMax(s, red);
    float e = expf(s - mx);
    sc[t] = e;
    float sum = blockSum(e, red);

    int d = t & 63, gp = t >> 6;
    const float* vb0 = g_kv + (size_t)(b * Eq) * (2 * Dq) + Dq + h * DHq + d;
    float acc = 0.f;
    #pragma unroll 4
    for (int e2 = gp * 64; e2 < gp * 64 + 64; e2++)
        acc += sc[e2] * vb0[(size_t)e2 * (2 * Dq)];
    outp[gp][d] = acc;
    __syncthreads();
    if (t < DHq) {
        float o = (outp[0][t] + outp[1][t] + outp[2][t] + outp[3][t]) / sum;
        splitw(o, g_mem_h, g_mem_l, (size_t)bm * Dq + h * DHq + t);
    }
}

// ---------------- no-edge mask + split for final proj ----------------
__global__ void memmask_k() {
    int i = blockIdx.x * 256 + threadIdx.x;
    int b = i / (Mq * Dq);
    splitw(g_mem2[i] * g_noedge[b], g_m2_h, g_m2_l, i);
}

// ---------------- launch ----------------
extern "C" void kernel_launch(void* const* d_in, const int* in_sizes, int n_in,
                              void* d_out, int out_size)
{
    const int*   edge_ids  = (const int*)  d_in[0];
    const int*   neigh_ids = (const int*)  d_in[1];
    const float* edge_mask = (const float*)d_in[2];
    const float* rel_emb   = (const float*)d_in[3];
    const float* rp_w      = (const float*)d_in[4];
    const float* rp_b      = (const float*)d_in[5];
    const float* ly_vw     = (const float*)d_in[6];
    const float* ly_vb     = (const float*)d_in[7];
    const float* ly_ow     = (const float*)d_in[8];
    const float* ly_ob     = (const float*)d_in[9];
    const float* ly_n1g    = (const float*)d_in[10];
    const float* ly_n1b    = (const float*)d_in[11];
    const float* ly_n2g    = (const float*)d_in[12];
    const float* ly_n2b    = (const float*)d_in[13];
    const float* ly_w1     = (const float*)d_in[14];
    const float* ly_b1     = (const float*)d_in[15];
    const float* ly_w2     = (const float*)d_in[16];
    const float* ly_b2     = (const float*)d_in[17];
    const float* mem_q     = (const float*)d_in[18];
    const float* t_qw      = (const float*)d_in[19];
    const float* t_qb      = (const float*)d_in[20];
    const float* t_kw      = (const float*)d_in[21];
    const float* t_kb      = (const float*)d_in[22];
    const float* t_vw      = (const float*)d_in[23];
    const float* t_vb      = (const float*)d_in[24];
    const float* t_ow      = (const float*)d_in[25];
    const float* t_ob      = (const float*)d_in[26];
    const float* proj_w    = (const float*)d_in[27];
    const float* proj_b    = (const float*)d_in[28];
    float* out = (float*)d_out;

    float *p_proj, *p_states, *p_t2, *p_kv, *p_kvb, *p_q, *p_mem2, *p_vwT, *p_cb, *p_zero;
    cudaGetSymbolAddress((void**)&p_proj,   g_proj);
    cudaGetSymbolAddress((void**)&p_states, g_states);
    cudaGetSymbolAddress((void**)&p_t2,     g_t2);
    cudaGetSymbolAddress((void**)&p_kv,     g_kv);
    cudaGetSymbolAddress((void**)&p_kvb,    g_kvb);
    cudaGetSymbolAddress((void**)&p_q,      g_q);
    cudaGetSymbolAddress((void**)&p_mem2,   g_mem2);
    cudaGetSymbolAddress((void**)&p_vwT,    g_vwT);
    cudaGetSymbolAddress((void**)&p_cb,     g_cb);
    cudaGetSymbolAddress((void**)&p_zero,   g_zero512);

    __nv_bfloat16 *p_agg_h, *p_agg_l, *p_st_h, *p_st_l, *p_hid_h, *p_hid_l;
    __nv_bfloat16 *p_mem_h, *p_mem_l, *p_m2_h, *p_m2_l;
    cudaGetSymbolAddress((void**)&p_agg_h,  g_agg_h);
    cudaGetSymbolAddress((void**)&p_agg_l,  g_agg_l);
    cudaGetSymbolAddress((void**)&p_st_h,   g_st_h);
    cudaGetSymbolAddress((void**)&p_st_l,   g_st_l);
    cudaGetSymbolAddress((void**)&p_hid_h,  g_hid_h);
    cudaGetSymbolAddress((void**)&p_hid_l,  g_hid_l);
    cudaGetSymbolAddress((void**)&p_mem_h,  g_mem_h);
    cudaGetSymbolAddress((void**)&p_mem_l,  g_mem_l);
    cudaGetSymbolAddress((void**)&p_m2_h,   g_m2_h);
    cudaGetSymbolAddress((void**)&p_m2_l,   g_m2_l);

    __nv_bfloat16 *p_emb_h, *p_emb_l, *p_rpw_h, *p_rpw_l, *p_ow_h, *p_ow_l, *p_vwT_h, *p_vwT_l;
    __nv_bfloat16 *p_wc_h, *p_wc_l, *p_w1_h, *p_w1_l, *p_w2_h, *p_w2_l;
    __nv_bfloat16 *p_kvw_h, *p_kvw_l, *p_to_h, *p_to_l, *p_pw_h, *p_pw_l;
    cudaGetSymbolAddress((void**)&p_emb_h, g_emb_h);
    cudaGetSymbolAddress((void**)&p_emb_l, g_emb_l);
    cudaGetSymbolAddress((void**)&p_rpw_h, g_rpw_h);
    cudaGetSymbolAddress((void**)&p_rpw_l, g_rpw_l);
    cudaGetSymbolAddress((void**)&p_ow_h,  g_ow_h);
    cudaGetSymbolAddress((void**)&p_ow_l,  g_ow_l);
    cudaGetSymbolAddress((void**)&p_vwT_h, g_vwT_h);
    cudaGetSymbolAddress((void**)&p_vwT_l, g_vwT_l);
    cudaGetSymbolAddress((void**)&p_wc_h,  g_wc_h);
    cudaGetSymbolAddress((void**)&p_wc_l,  g_wc_l);
    cudaGetSymbolAddress((void**)&p_w1_h,  g_w1_h);
    cudaGetSymbolAddress((void**)&p_w1_l,  g_w1_l);
    cudaGetSymbolAddress((void**)&p_w2_h,  g_w2_h);
    cudaGetSymbolAddress((void**)&p_w2_l,  g_w2_l);
    cudaGetSymbolAddress((void**)&p_kvw_h, g_kvw_h);
    cudaGetSymbolAddress((void**)&p_kvw_l, g_kvw_l);
    cudaGetSymbolAddress((void**)&p_to_h,  g_to_h);
    cudaGetSymbolAddress((void**)&p_to_l,  g_to_l);
    cudaGetSymbolAddress((void**)&p_pw_h,  g_pw_h);
    cudaGetSymbolAddress((void**)&p_pw_l,  g_pw_l);

    constexpr int DD = Dq * Dq, DD4 = 4 * Dq * Dq;

    // R6-proven configs for the layer chain; 512-thr only for relproj (measured faster).
    auto kA   = mma_nt<128,64,4,2,256, 0,false,false,true>;   // Wc: split out
    auto kB   = mma_nt<128,64,4,2,256, 0,true ,true ,false>;  // res + f32 out
    auto kC   = mma_nt<128,128,2,4,256, 1,false,false,true>;  // gelu + split out
    auto kD   = mma_nt<128,64,4,2,256, 0,false,true ,false>;  // f32 out
    auto kDrp = mma_nt<128,64,4,4,512, 0,false,true ,false>;  // relproj (512 thr)
    constexpr int SM64  = (128 + 64)  * PADK * 2 * NSTG;
    constexpr int SM128 = (128 + 128) * PADK * 2 * NSTG;
    cudaFuncSetAttribute(kA,   cudaFuncAttributeMaxDynamicSharedMemorySize, SM64);
    cudaFuncSetAttribute(kB,   cudaFuncAttributeMaxDynamicSharedMemorySize, SM64);
    cudaFuncSetAttribute(kC,   cudaFuncAttributeMaxDynamicSharedMemorySize, SM128);
    cudaFuncSetAttribute(kD,   cudaFuncAttributeMaxDynamicSharedMemorySize, SM64);
    cudaFuncSetAttribute(kDrp, cudaFuncAttributeMaxDynamicSharedMemorySize, SM64);

    // one-time stream/event creation (host resources; no device memory)
    static cudaStream_t s2 = nullptr;
    static cudaEvent_t e0 = nullptr, e1 = nullptr;
    if (!s2) {
        cudaStreamCreateWithFlags(&s2, cudaStreamNonBlocking);
        cudaEventCreateWithFlags(&e0, cudaEventDisableTiming);
        cudaEventCreateWithFlags(&e1, cudaEventDisableTiming);
    }

    // ---- fork: s2 handles weight prep concurrently with relproj/sims chain ----
    cudaEventRecord(e0, 0);
    cudaStreamWaitEvent(s2, e0, 0);

    // S2: fold prep, big splits, Wc, q-proj, kv bias, noedge
    fold_prep_k<<<dim3(16,16,Lq), 256, 0, s2>>>(ly_vw, ly_ow, ly_vb, ly_ob, p_vwT, p_cb);
    {
        SplitArgs sa;
        int s = 0, tot = 0;
        auto add = [&](const float* src, __nv_bfloat16* h, __nv_bfloat16* l, int n) {
            sa.seg[s++] = SplitSeg{src, h, l, n}; tot += n;
        };
        for (int l = 0; l < Lq; l++) {
            add(ly_w1 + (size_t)l * DD4, p_w1_h + (size_t)l * DD4, p_w1_l + (size_t)l * DD4, DD4);
            add(ly_w2 + (size_t)l * DD4, p_w2_h + (size_t)l * DD4, p_w2_l + (size_t)l * DD4, DD4);
            add(ly_ow + (size_t)l * DD,  p_ow_h + (size_t)l * DD,  p_ow_l + (size_t)l * DD,  DD);
            add(p_vwT + (size_t)l * DD,  p_vwT_h + (size_t)l * DD, p_vwT_l + (size_t)l * DD, DD);
        }
        add(t_kw,   p_kvw_h,      p_kvw_l,      DD);
        add(t_vw,   p_kvw_h + DD, p_kvw_l + DD, DD);
        add(t_ow,   p_to_h,       p_to_l,       DD);
        add(proj_w, p_pw_h,       p_pw_l,       HLLMq * Dq);
        sa.total = tot;
        split_all_k<<<(tot + 255) / 256, 256, 0, s2>>>(sa);
    }
    for (int l = 0; l < Lq; l++)
        kA<<<dim3(Dq/64, Dq/128), 256, SM64, s2>>>(
            p_ow_h + (size_t)l*DD, p_ow_l + (size_t)l*DD,
            p_vwT_h + (size_t)l*DD, p_vwT_l + (size_t)l*DD,
            p_zero, nullptr, nullptr, p_wc_h + (size_t)l*DD, p_wc_l + (size_t)l*DD, Dq, Dq, Dq);
    gemm_nt<0,true,false><<<dim3(Dq/64, 1), 256, 0, s2>>>(mem_q, t_qw, t_qb, p_q, nullptr, nullptr,
                                                          Mq, Dq, Dq);
    pack_kvb_k<<<4, 256, 0, s2>>>(t_kb, t_vb);
    noedge_k<<<Bq, 256, 0, s2>>>(edge_mask);
    cudaEventRecord(e1, s2);

    // S0 (main): split emb/rpw only -> relation projection -> sims/top-k/agg
    {
        SplitArgs sa;
        sa.seg[0] = SplitSeg{rel_emb, p_emb_h, p_emb_l, Rq * RDq};
        sa.seg[1] = SplitSeg{rp_w,    p_rpw_h, p_rpw_l, Dq * RDq};
        sa.total = Rq * RDq + Dq * RDq;
        split_all_k<<<(sa.total + 255) / 256, 256>>>(sa);
    }
    kDrp<<<dim3(Dq/64, RPAD/128), 512, SM64>>>(
        p_emb_h, p_emb_l, p_rpw_h, p_rpw_l, rp_b, nullptr, p_proj, nullptr, nullptr,
        RPAD, Dq, RDq);
    sims_agg_k<<<BEq, 256>>>(edge_ids, neigh_ids);

    // ---- join: layer chain needs Wc/w1/w2 from s2 ----
    cudaStreamWaitEvent(0, e1, 0);

    // relation-context layers
    for (int l = 0; l < Lq; l++) {
        kB<<<dim3(Dq/64, BEq/128), 256, SM64>>>(
            p_agg_h, p_agg_l, p_wc_h + (size_t)l*DD, p_wc_l + (size_t)l*DD,
            p_cb + l*Dq, p_states, p_t2, nullptr, nullptr, BEq, Dq, Dq);
        ln_k<false><<<BEq, 256>>>(p_t2, ly_n1g + l*Dq, ly_n1b + l*Dq, nullptr,
                                  p_states, p_st_h, p_st_l);

        kC<<<dim3(4*Dq/128, BEq/128), 256, SM128>>>(
            p_st_h, p_st_l, p_w1_h + (size_t)l*DD4, p_w1_l + (size_t)l*DD4,
            ly_b1 + l*4*Dq, nullptr, nullptr, p_hid_h, p_hid_l, BEq, 4*Dq, Dq);

        kB<<<dim3(Dq/64, BEq/128), 256, SM64>>>(
            p_hid_h, p_hid_l, p_w2_h + (size_t)l*DD4, p_w2_l + (size_t)l*DD4,
            ly_b2 + l*Dq, p_states, p_t2, nullptr, nullptr, BEq, Dq, 4*Dq);
        ln_k<true><<<BEq, 256>>>(p_t2, ly_n2g + l*Dq, ly_n2b + l*Dq, edge_mask,
                                 p_states, p_st_h, p_st_l);
    }

    // tokenizer K|V projection (combined)
    kD<<<dim3(2*Dq/64, BEq/128), 256, SM64>>>(
        p_st_h, p_st_l, p_kvw_h, p_kvw_l, p_kvb, nullptr, p_kv, nullptr, nullptr, BEq, 2*Dq, Dq);

    // attention + output proj + masking
    attn_k<<<Bq * Mq * Hq, 256>>>(edge_mask);
    kD<<<dim3(Dq/64, (Bq*Mq)/128), 256, SM64>>>(
        p_mem_h, p_mem_l, p_to_h, p_to_l, t_ob, nullptr, p_mem2, nullptr, nullptr, Bq*Mq, Dq, Dq);
    memmask_k<<<(Bq*Mq*Dq)/256, 256>>>();

    // LLM projection -> d_out
    kD<<<dim3(HLLMq/64, (Bq*Mq)/128), 256, SM64>>>(
        p_m2_h, p_m2_l, p_pw_h, p_pw_l, proj_b, nullptr, out, nullptr, nullptr, Bq*Mq, HLLMq, Dq);
}

// round 13
// speedup vs baseline: 1.7345x; 1.1015x over previous
#include <cuda_runtime.h>
#include <cuda_bf16.h>
#include <math.h>
#include <float.h>
#include <stdint.h>

// ---------------- problem constants ----------------
constexpr int Bq = 8, Eq = 256, Nq = 32;
constexpr int Dq = 512, RDq = 768, Rq = 2000;
constexpr int Lq = 2, Kq = 8, Mq = 32, Hq = 8, DHq = 64;
constexpr int HLLMq = 4096;
constexpr int BEq = Bq * Eq;          // 2048 edge tokens
constexpr int RPAD = 2048;            // rel rows padded to TM multiple
constexpr float EPSq = 1e-5f;

// ---------------- scratch (device globals; no allocs allowed) ----------------
__device__ float g_proj  [RPAD * Dq];
__device__ float g_states[BEq * Dq];
__device__ float g_t2    [BEq * Dq];
__device__ float g_kv    [BEq * 2 * Dq];
__device__ float g_kvb   [2 * Dq];
__device__ float g_q     [Mq * Dq];
__device__ float g_mem2  [Bq * Mq * Dq];
__device__ float g_noedge[Bq];
__device__ float g_vwT   [Lq][Dq * Dq];
__device__ float g_cb    [Lq][Dq];
__device__ float g_zero512[Dq];
// bf16 hi/lo split activation buffers
__device__ __align__(256) __nv_bfloat16 g_agg_h[BEq * Dq],      g_agg_l[BEq * Dq];
__device__ __align__(256) __nv_bfloat16 g_st_h [BEq * Dq],      g_st_l [BEq * Dq];
__device__ __align__(256) __nv_bfloat16 g_hid_h[BEq * 4 * Dq],  g_hid_l[BEq * 4 * Dq];
__device__ __align__(256) __nv_bfloat16 g_mem_h[Bq * Mq * Dq],  g_mem_l[Bq * Mq * Dq];
__device__ __align__(256) __nv_bfloat16 g_m2_h [Bq * Mq * Dq],  g_m2_l [Bq * Mq * Dq];
// bf16 hi/lo split weight buffers
__device__ __align__(256) __nv_bfloat16 g_emb_h[RPAD * RDq],     g_emb_l[RPAD * RDq];
__device__ __align__(256) __nv_bfloat16 g_rpw_h[Dq * RDq],       g_rpw_l[Dq * RDq];
__device__ __align__(256) __nv_bfloat16 g_ow_h[Lq][Dq * Dq],     g_ow_l[Lq][Dq * Dq];
__device__ __align__(256) __nv_bfloat16 g_vwT_h[Lq][Dq * Dq],    g_vwT_l[Lq][Dq * Dq];
__device__ __align__(256) __nv_bfloat16 g_wc_h[Lq][Dq * Dq],     g_wc_l[Lq][Dq * Dq];
__device__ __align__(256) __nv_bfloat16 g_w1_h[Lq][4 * Dq * Dq], g_w1_l[Lq][4 * Dq * Dq];
__device__ __align__(256) __nv_bfloat16 g_w2_h[Lq][4 * Dq * Dq], g_w2_l[Lq][4 * Dq * Dq];
__device__ __align__(256) __nv_bfloat16 g_kvw_h[2 * Dq * Dq],    g_kvw_l[2 * Dq * Dq];
__device__ __align__(256) __nv_bfloat16 g_to_h[Dq * Dq],         g_to_l[Dq * Dq];
__device__ __align__(256) __nv_bfloat16 g_pw_h[HLLMq * Dq],      g_pw_l[HLLMq * Dq];

__device__ __forceinline__ void splitw(float v, __nv_bfloat16* H, __nv_bfloat16* L, size_t i) {
    __nv_bfloat16 h = __float2bfloat16(v);
    H[i] = h;
    L[i] = __float2bfloat16(v - __bfloat162float(h));
}

__device__ __forceinline__ uint32_t smem_u32(const void* p) {
    uint32_t a;
    asm("{ .reg .u64 t; cvta.to.shared.u64 t, %1; cvt.u32.u64 %0, t; }" : "=r"(a) : "l"(p));
    return a;
}

// ---------------- reductions ----------------
__device__ __forceinline__ float warpSum(float v) {
    #pragma unroll
    for (int o = 16; o; o >>= 1) v += __shfl_xor_sync(0xffffffffu, v, o);
    return v;
}
__device__ __forceinline__ float warpMax(float v) {
    #pragma unroll
    for (int o = 16; o; o >>= 1) v = fmaxf(v, __shfl_xor_sync(0xffffffffu, v, o));
    return v;
}
__device__ __forceinline__ float blockSum(float v, float* red) {
    int lane = threadIdx.x & 31, w = threadIdx.x >> 5;
    int nw = blockDim.x >> 5;
    v = warpSum(v);
    if (lane == 0) red[w] = v;
    __syncthreads();
    if (w == 0) {
        float r = (lane < nw) ? red[lane] : 0.f;
        r = warpSum(r);
        if (lane == 0) red[0] = r;
    }
    __syncthreads();
    float out = red[0];
    __syncthreads();
    return out;
}
__device__ __forceinline__ float blockMax(float v, float* red) {
    int lane = threadIdx.x & 31, w = threadIdx.x >> 5;
    int nw = blockDim.x >> 5;
    v = warpMax(v);
    if (lane == 0) red[w] = v;
    __syncthreads();
    if (w == 0) {
        float r = (lane < nw) ? red[lane] : -FLT_MAX;
        r = warpMax(r);
        if (lane == 0) red[0] = r;
    }
    __syncthreads();
    float out = red[0];
    __syncthreads();
    return out;
}

// ---------------- mma.sync primitives ----------------
__device__ __forceinline__ void mma16816(float* d, const uint32_t* a, const uint32_t* b) {
    asm volatile("mma.sync.aligned.m16n8k16.row.col.f32.bf16.bf16.f32 "
        "{%0,%1,%2,%3}, {%4,%5,%6,%7}, {%8,%9}, {%0,%1,%2,%3};"
        : "+f"(d[0]), "+f"(d[1]), "+f"(d[2]), "+f"(d[3])
        : "r"(a[0]), "r"(a[1]), "r"(a[2]), "r"(a[3]), "r"(b[0]), "r"(b[1]));
}
__device__ __forceinline__ void ldsm4(uint32_t& r0, uint32_t& r1, uint32_t& r2, uint32_t& r3,
                                      uint32_t addr) {
    asm volatile("ldmatrix.sync.aligned.m8n8.x4.shared.b16 {%0,%1,%2,%3}, [%4];"
        : "=r"(r0), "=r"(r1), "=r"(r2), "=r"(r3) : "r"(addr));
}
__device__ __forceinline__ void cpasync16(uint32_t dst, const void* src) {
    asm volatile("cp.async.cg.shared.global [%0], [%1], 16;\n" :: "r"(dst), "l"(src) : "memory");
}

// ================= bf16x3 NT GEMM via mma.sync, BK=64, 4-stage pipeline =================
constexpr int PADK = 72;
constexpr int NSTG = 4;

template<int TM, int TN, int WR, int WC, int NTHR, int ACT, bool RES, bool WF32, bool WSPLIT>
__global__ __launch_bounds__(NTHR)
void mma_nt(const __nv_bfloat16* __restrict__ Ah, const __nv_bfloat16* __restrict__ Al,
            const __nv_bfloat16* __restrict__ Bh, const __nv_bfloat16* __restrict__ Bl,
            const float* __restrict__ bias, const float* __restrict__ res,
            float* __restrict__ Cf, __nv_bfloat16* __restrict__ Ch, __nv_bfloat16* __restrict__ Cl,
            int M, int N, int K)
{
    static_assert(WR * WC == NTHR / 32, "warp grid must cover block");
    extern __shared__ __align__(128) __nv_bfloat16 smem[];
    constexpr int STG_E = (TM + TN) * PADK;
    constexpr int tm = TM / WR, tn = TN / WC;
    constexpr int MT = tm / 16, NT = tn / 8;

    const int tid = threadIdx.x;
    const int wid = tid >> 5, lane = tid & 31;
    const int bm = blockIdx.y * TM, bn = blockIdx.x * TN;
    const int wm = (wid / WC) * tm, wn = (wid % WC) * tn;
    const uint32_t sbase = smem_u32(smem);

    const int NI = (3 * K) / 64;

    auto load_stage = [&](int stage, int buf) {
        int c0 = stage * 64;
        int term = c0 / K;
        int kk = c0 - term * K;
        const __nv_bfloat16* As = (term < 2) ? Ah : Al;
        const __nv_bfloat16* Bs = (term == 1) ? Bl : Bh;
        uint32_t base = sbase + (uint32_t)buf * STG_E * 2;
        constexpr int CHA = TM * 8, CH = (TM + TN) * 8;
        #pragma unroll
        for (int j = 0; j < CH / NTHR; ++j) {
            int f = tid + NTHR * j;
            if (f < CHA) {
                int row = f >> 3, ch = f & 7;
                cpasync16(base + (uint32_t)(row * PADK + ch * 8) * 2,
                          As + (size_t)(bm + row) * K + kk + ch * 8);
            } else {
                int f2 = f - CHA;
                int row = f2 >> 3, ch = f2 & 7;
                cpasync16(base + (uint32_t)(TM * PADK + row * PADK + ch * 8) * 2,
                          Bs + (size_t)(bn + row) * K + kk + ch * 8);
            }
        }
        asm volatile("cp.async.commit_group;\n" ::: "memory");
    };

    float d[MT][NT][4];
    #pragma unroll
    for (int a = 0; a < MT; a++)
        #pragma unroll
        for (int b = 0; b < NT; b++)
            #pragma unroll
            for (int c = 0; c < 4; c++) d[a][b][c] = 0.f;

    load_stage(0, 0);
    load_stage(1, 1);
    load_stage(2, 2);

    const int a_lrow = lane & 15, a_lk = (lane >> 4) * 8;
    const int bq = lane >> 3;
    const int b_lrow = (lane & 7) + ((bq >> 1) * 8);
    const int b_lk = (bq & 1) * 8;

    for (int i = 0; i < NI; ++i) {
        if (i + 3 <= NI)      asm volatile("cp.async.wait_group 2;\n" ::: "memory");
        else if (i + 2 == NI) asm volatile("cp.async.wait_group 1;\n" ::: "memory");
        else                  asm volatile("cp.async.wait_group 0;\n" ::: "memory");
        __syncthreads();

        if (i + 3 < NI) load_stage(i + 3, (i + 3) & (NSTG - 1));

        const uint32_t abase = sbase + (uint32_t)(i & (NSTG - 1)) * STG_E * 2;
        const uint32_t bbase = abase + TM * PADK * 2;

        #pragma unroll
        for (int kh = 0; kh < 4; ++kh) {
            const int kc = kh * 16;
            uint32_t afr[MT][4];
            #pragma unroll
            for (int mt = 0; mt < MT; ++mt)
                ldsm4(afr[mt][0], afr[mt][1], afr[mt][2], afr[mt][3],
                      abase + (uint32_t)((wm + mt * 16 + a_lrow) * PADK + kc + a_lk) * 2);
            uint32_t bfr[NT][2];
            #pragma unroll
            for (int nt2 = 0; nt2 < NT / 2; ++nt2) {
                uint32_t r0, r1, r2, r3;
                ldsm4(r0, r1, r2, r3,
                      bbase + (uint32_t)((wn + nt2 * 16 + b_lrow) * PADK + kc + b_lk) * 2);
                bfr[nt2 * 2][0] = r0; bfr[nt2 * 2][1] = r1;
                bfr[nt2 * 2 + 1][0] = r2; bfr[nt2 * 2 + 1][1] = r3;
            }
            #pragma unroll
            for (int mt = 0; mt < MT; ++mt)
                #pragma unroll
                for (int nt = 0; nt < NT; ++nt)
                    mma16816(d[mt][nt], afr[mt], bfr[nt]);
        }
    }

    const int erow = lane >> 2, ecol = (lane & 3) * 2;
    #pragma unroll
    for (int mt = 0; mt < MT; ++mt) {
        #pragma unroll
        for (int h = 0; h < 2; ++h) {
            const int row = bm + wm + mt * 16 + erow + h * 8;
            #pragma unroll
            for (int nt = 0; nt < NT; ++nt) {
                const int n = bn + wn + nt * 8 + ecol;
                float v0 = d[mt][nt][h * 2 + 0];
                float v1 = d[mt][nt][h * 2 + 1];
                float2 bv = *(const float2*)(bias + n);
                v0 += bv.x; v1 += bv.y;
                if (RES) {
                    float2 rv = *(const float2*)(res + (size_t)row * N + n);
                    v0 += rv.x; v1 += rv.y;
                }
                if (ACT == 1) {
                    v0 = 0.5f * v0 * (1.0f + erff(v0 * 0.70710678118654752f));
                    v1 = 0.5f * v1 * (1.0f + erff(v1 * 0.70710678118654752f));
                }
                if (WF32)
                    *(float2*)(Cf + (size_t)row * N + n) = make_float2(v0, v1);
                if (WSPLIT) {
                    __nv_bfloat16 h0 = __float2bfloat16(v0), h1 = __float2bfloat16(v1);
                    __nv_bfloat16 l0 = __float2bfloat16(v0 - __bfloat162float(h0));
                    __nv_bfloat16 l1 = __float2bfloat16(v1 - __bfloat162float(h1));
                    uint32_t hp = ((uint32_t)__bfloat16_as_ushort(h1) << 16) | __bfloat16_as_ushort(h0);
                    uint32_t lp = ((uint32_t)__bfloat16_as_ushort(l1) << 16) | __bfloat16_as_ushort(l0);
                    *(uint32_t*)(Ch + (size_t)row * N + n) = hp;
                    *(uint32_t*)(Cl + (size_t)row * N + n) = lp;
                }
            }
        }
    }
}

// ---------------- fp32 SIMT NT GEMM (q-proj only) ----------------
template<int ACT, bool WF32, bool WSPLIT>
__global__ void gemm_nt(const float* __restrict__ A, const float* __restrict__ W,
                        const float* __restrict__ bias,
                        float* __restrict__ C, __nv_bfloat16* __restrict__ Ch,
                        __nv_bfloat16* __restrict__ Cl, int M, int N, int K)
{
    __shared__ float As[16][68];
    __shared__ float Ws[16][68];
    const int t  = threadIdx.x;
    const int bm = blockIdx.y * 64, bn = blockIdx.x * 64;
    const int lr = t >> 2, lk = (t & 3) * 4;
    const int ty = t >> 4, tx = t & 15;
    float acc[4][4] = {};

    for (int k0 = 0; k0 < K; k0 += 16) {
        int am = bm + lr;
        float4 av = make_float4(0.f, 0.f, 0.f, 0.f);
        if (am < M) av = *(const float4*)(A + (size_t)am * K + k0 + lk);
        As[lk + 0][lr] = av.x; As[lk + 1][lr] = av.y;
        As[lk + 2][lr] = av.z; As[lk + 3][lr] = av.w;
        int wn = bn + lr;
        float4 wv = make_float4(0.f, 0.f, 0.f, 0.f);
        if (wn < N) wv = *(const float4*)(W + (size_t)wn * K + k0 + lk);
        Ws[lk + 0][lr] = wv.x; Ws[lk + 1][lr] = wv.y;
        Ws[lk + 2][lr] = wv.z; Ws[lk + 3][lr] = wv.w;
        __syncthreads();
        #pragma unroll
        for (int kk = 0; kk < 16; kk++) {
            float4 a = *(const float4*)&As[kk][ty * 4];
            float4 b = *(const float4*)&Ws[kk][tx * 4];
            float av4[4] = {a.x, a.y, a.z, a.w};
            float bv4[4] = {b.x, b.y, b.z, b.w};
            #pragma unroll
            for (int i = 0; i < 4; i++)
                #pragma unroll
                for (int j = 0; j < 4; j++)
                    acc[i][j] += av4[i] * bv4[j];
        }
        __syncthreads();
    }
    #pragma unroll
    for (int i = 0; i < 4; i++) {
        int m = bm + ty * 4 + i;
        if (m >= M) continue;
        #pragma unroll
        for (int j = 0; j < 4; j++) {
            int n = bn + tx * 4 + j;
            if (n >= N) continue;
            float v = acc[i][j] + bias[n];
            if (ACT == 1) v = 0.5f * v * (1.0f + erff(v * 0.70710678118654752f));
            if (WF32) C[(size_t)m * N + n] = v;
            if (WSPLIT) splitw(v, Ch, Cl, (size_t)m * N + n);
        }
    }
}

// ---------------- fold prep (both layers via blockIdx.z) ----------------
__global__ void fold_prep_k(const float* __restrict__ vw0, const float* __restrict__ ow0,
                            const float* __restrict__ vb0, const float* __restrict__ ob0,
                            float* __restrict__ vwT0, float* __restrict__ cb0)
{
    const int lz = blockIdx.z;
    const float* vw = vw0 + (size_t)lz * Dq * Dq;
    const float* ow = ow0 + (size_t)lz * Dq * Dq;
    const float* vb = vb0 + lz * Dq;
    const float* ob = ob0 + lz * Dq;
    float* vwT = vwT0 + (size_t)lz * Dq * Dq;
    float* cb  = cb0 + lz * Dq;

    __shared__ float tile[32][33];
    const int bx = blockIdx.x, by = blockIdx.y;
    const int t = threadIdx.x;
    const int tx = t & 31, ty = t >> 5;
    #pragma unroll
    for (int r = 0; r < 4; r++)
        tile[ty + r * 8][tx] = vw[(size_t)(by * 32 + ty + r * 8) * Dq + bx * 32 + tx];
    __syncthreads();
    #pragma unroll
    for (int r = 0; r < 4; r++)
        vwT[(size_t)(bx * 32 + ty + r * 8) * Dq + by * 32 + tx] = tile[tx][ty + r * 8];

    if (by == 0) {
        int n = bx * 32 + (t >> 3), ks = t & 7;
        float p = 0.f;
        for (int k = ks * 64; k < ks * 64 + 64; k++) p += ow[(size_t)n * Dq + k] * vb[k];
        p += __shfl_xor_sync(0xffffffffu, p, 1);
        p += __shfl_xor_sync(0xffffffffu, p, 2);
        p += __shfl_xor_sync(0xffffffffu, p, 4);
        if (ks == 0) cb[n] = p + ob[n];
    }
}

// ---------------- fused weight split, vectorized x4 ----------------
// seg[].n is in float4 units; all segments 16B-aligned and length % 4 == 0.
struct SplitSeg { const float* src; __nv_bfloat16* h; __nv_bfloat16* l; int n; };
struct SplitArgs { SplitSeg seg[8]; int total; };

__global__ void split_all4_k(SplitArgs a) {
    int i = blockIdx.x * 256 + threadIdx.x;
    if (i >= a.total) return;
    int idx = i, s = 0;
    while (idx >= a.seg[s].n) { idx -= a.seg[s].n; s++; }
    float4 v = ((const float4*)a.seg[s].src)[idx];
    float vv[4] = {v.x, v.y, v.z, v.w};
    uint16_t hb[4], lb[4];
    #pragma unroll
    for (int j = 0; j < 4; j++) {
        __nv_bfloat16 h = __float2bfloat16(vv[j]);
        hb[j] = __bfloat16_as_ushort(h);
        lb[j] = __bfloat16_as_ushort(__float2bfloat16(vv[j] - __bfloat162float(h)));
    }
    uint2 hp, lp;
    hp.x = ((uint32_t)hb[1] << 16) | hb[0];
    hp.y = ((uint32_t)hb[3] << 16) | hb[2];
    lp.x = ((uint32_t)lb[1] << 16) | lb[0];
    lp.y = ((uint32_t)lb[3] << 16) | lb[2];
    ((uint2*)a.seg[s].h)[idx] = hp;
    ((uint2*)a.seg[s].l)[idx] = lp;
}

// ---------------- sims + inline norms + top-k + agg(split) + states init ----------------
__global__ void sims_agg_k(const int* __restrict__ eids, const int* __restrict__ nids)
{
    int be = blockIdx.x, t = threadIdx.x;
    int lane = t & 31, w = t >> 5;
    __shared__ float se[Dq];
    __shared__ float ssim[Nq];
    __shared__ int   snid[Nq];
    __shared__ int   ssel[Kq];
    __shared__ float red[32];

    int eid = eids[be];
    float sq = 0.f;
    for (int d = t; d < Dq; d += 256) {
        float x = g_proj[eid * Dq + d];
        se[d] = x;
        g_states[(size_t)be * Dq + d] = x;
        sq += x * x;
    }
    float en = fmaxf(sqrtf(blockSum(sq, red)), 1e-12f);

    for (int n = w; n < Nq; n += 8) {
        int nid = nids[be * Nq + n];
        float s = 0.f, q = 0.f;
        for (int d = lane; d < Dq; d += 32) {
            float p = g_proj[nid * Dq + d];
            s += p * se[d];
            q += p * p;
        }
        s = warpSum(s); q = warpSum(q);
        if (lane == 0) {
            snid[n] = nid;
            ssim[n] = s / (fmaxf(sqrtf(q), 1e-12f) * en);
        }
    }
    __syncthreads();

    if (w == 0) {
        float sv = ssim[lane];
        for (int it = 0; it < Kq; it++) {
            float bs = sv; int bi = lane;
            #pragma unroll
            for (int o = 16; o; o >>= 1) {
                float os = __shfl_xor_sync(0xffffffffu, bs, o);
                int   oi = __shfl_xor_sync(0xffffffffu, bi, o);
                if (os > bs || (os == bs && oi < bi)) { bs = os; bi = oi; }
            }
            if (lane == bi) sv = -FLT_MAX;
            if (lane == 0) ssel[it] = snid[bi];
        }
    }
    __syncthreads();

    for (int d = t; d < Dq; d += 256) {
        float a = 0.f;
        #pragma unroll
        for (int k2 = 0; k2 < Kq; k2++) a += g_proj[ssel[k2] * Dq + d];
        splitw(a * (1.0f / Kq), g_agg_h, g_agg_l, (size_t)be * Dq + d);
    }
}

// ---------------- layernorm -> fp32 states + hi/lo split ----------------
template<bool MASK>
__global__ void ln_k(const float* __restrict__ in, const float* __restrict__ g,
                     const float* __restrict__ b, const float* __restrict__ mask,
                     float* __restrict__ out, __nv_bfloat16* __restrict__ oh,
                     __nv_bfloat16* __restrict__ ol)
{
    int be = blockIdx.x, t = threadIdx.x;
    __shared__ float red[32];
    const float* x = in + (size_t)be * Dq;
    float v0 = x[t], v1 = x[t + 256];
    float mu = blockSum(v0 + v1, red) * (1.0f / Dq);
    float d0 = v0 - mu, d1 = v1 - mu;
    float var = blockSum(d0 * d0 + d1 * d1, red) * (1.0f / Dq);
    float r = rsqrtf(var + EPSq);
    float mk = MASK ? mask[be] : 1.0f;
    float o0 = (d0 * r * g[t      ] + b[t      ]) * mk;
    float o1 = (d1 * r * g[t + 256] + b[t + 256]) * mk;
    size_t i0 = (size_t)be * Dq + t, i1 = i0 + 256;
    out[i0] = o0; out[i1] = o1;
    splitw(o0, oh, ol, i0);
    splitw(o1, oh, ol, i1);
}

// ---------------- pack kv bias ----------------
__global__ void pack_kvb_k(const float* __restrict__ kb, const float* __restrict__ vb) {
    int i = blockIdx.x * 256 + threadIdx.x;
    g_kvb[i] = (i < Dq) ? kb[i] : vb[i - Dq];
}

// ---------------- no-edge flags ----------------
__global__ void noedge_k(const float* __restrict__ mask) {
    int b = blockIdx.x;
    __shared__ float red[32];
    float s = blockSum(mask[b * Eq + threadIdx.x], red);
    if (threadIdx.x == 0) g_noedge[b] = (s == 0.f) ? 0.f : 1.f;
}

// ---------------- memory-token cross attention, head-parallel ----------------
__global__ void attn_k(const float* __restrict__ mask)
{
    int bmh = blockIdx.x;
    int h = bmh & 7, bm = bmh >> 3;
    int b = bm >> 5, m = bm & 31;
    int t = threadIdx.x;
    __shared__ float qh[DHq];
    __shared__ float sc[Eq];
    __shared__ float red[32];
    __shared__ float outp[4][DHq];

    if (t < DHq) qh[t] = g_q[m * Dq + h * DHq + t];
    __syncthreads();

    const float* kr = g_kv + (size_t)(b * Eq + t) * (2 * Dq) + h * DHq;
    float dot = 0.f;
    #pragma unroll
    for (int d = 0; d < DHq; d++) dot += qh[d] * kr[d];
    float s = dot * 0.125f;
    if (mask[b * Eq + t] == 0.f) s = -FLT_MAX;

    float mx = blockMax(s, red);
    float e = expf(s - mx);
    sc[t] = e;
    float sum = blockSum(e, red);

    int d = t & 63, gp = t >> 6;
    const float* vb0 = g_kv + (size_t)(b * Eq) * (2 * Dq) + Dq + h * DHq + d;
    float acc = 0.f;
    #pragma unroll 4
    for (int e2 = gp * 64; e2 < gp * 64 + 64; e2++)
        acc += sc[e2] * vb0[(size_t)e2 * (2 * Dq)];
    outp[gp][d] = acc;
    __syncthreads();
    if (t < DHq) {
        float o = (outp[0][t] + outp[1][t] + outp[2][t] + outp[3][t]) / sum;
        splitw(o, g_mem_h, g_mem_l, (size_t)bm * Dq + h * DHq + t);
    }
}

// ---------------- no-edge mask + split for final proj ----------------
__global__ void memmask_k() {
    int i = blockIdx.x * 256 + threadIdx.x;
    int b = i / (Mq * Dq);
    splitw(g_mem2[i] * g_noedge[b], g_m2_h, g_m2_l, i);
}

// ---------------- launch ----------------
extern "C" void kernel_launch(void* const* d_in, const int* in_sizes, int n_in,
                              void* d_out, int out_size)
{
    const int*   edge_ids  = (const int*)  d_in[0];
    const int*   neigh_ids = (const int*)  d_in[1];
    const float* edge_mask = (const float*)d_in[2];
    const float* rel_emb   = (const float*)d_in[3];
    const float* rp_w      = (const float*)d_in[4];
    const float* rp_b      = (const float*)d_in[5];
    const float* ly_vw     = (const float*)d_in[6];
    const float* ly_vb     = (const float*)d_in[7];
    const float* ly_ow     = (const float*)d_in[8];
    const float* ly_ob     = (const float*)d_in[9];
    const float* ly_n1g    = (const float*)d_in[10];
    const float* ly_n1b    = (const float*)d_in[11];
    const float* ly_n2g    = (const float*)d_in[12];
    const float* ly_n2b    = (const float*)d_in[13];
    const float* ly_w1     = (const float*)d_in[14];
    const float* ly_b1     = (const float*)d_in[15];
    const float* ly_w2     = (const float*)d_in[16];
    const float* ly_b2     = (const float*)d_in[17];
    const float* mem_q     = (const float*)d_in[18];
    const float* t_qw      = (const float*)d_in[19];
    const float* t_qb      = (const float*)d_in[20];
    const float* t_kw      = (const float*)d_in[21];
    const float* t_kb      = (const float*)d_in[22];
    const float* t_vw      = (const float*)d_in[23];
    const float* t_vb      = (const float*)d_in[24];
    const float* t_ow      = (const float*)d_in[25];
    const float* t_ob      = (const float*)d_in[26];
    const float* proj_w    = (const float*)d_in[27];
    const float* proj_b    = (const float*)d_in[28];
    float* out = (float*)d_out;

    float *p_proj, *p_states, *p_t2, *p_kv, *p_kvb, *p_q, *p_mem2, *p_vwT, *p_cb, *p_zero;
    cudaGetSymbolAddress((void**)&p_proj,   g_proj);
    cudaGetSymbolAddress((void**)&p_states, g_states);
    cudaGetSymbolAddress((void**)&p_t2,     g_t2);
    cudaGetSymbolAddress((void**)&p_kv,     g_kv);
    cudaGetSymbolAddress((void**)&p_kvb,    g_kvb);
    cudaGetSymbolAddress((void**)&p_q,      g_q);
    cudaGetSymbolAddress((void**)&p_mem2,   g_mem2);
    cudaGetSymbolAddress((void**)&p_vwT,    g_vwT);
    cudaGetSymbolAddress((void**)&p_cb,     g_cb);
    cudaGetSymbolAddress((void**)&p_zero,   g_zero512);

    __nv_bfloat16 *p_agg_h, *p_agg_l, *p_st_h, *p_st_l, *p_hid_h, *p_hid_l;
    __nv_bfloat16 *p_mem_h, *p_mem_l, *p_m2_h, *p_m2_l;
    cudaGetSymbolAddress((void**)&p_agg_h,  g_agg_h);
    cudaGetSymbolAddress((void**)&p_agg_l,  g_agg_l);
    cudaGetSymbolAddress((void**)&p_st_h,   g_st_h);
    cudaGetSymbolAddress((void**)&p_st_l,   g_st_l);
    cudaGetSymbolAddress((void**)&p_hid_h,  g_hid_h);
    cudaGetSymbolAddress((void**)&p_hid_l,  g_hid_l);
    cudaGetSymbolAddress((void**)&p_mem_h,  g_mem_h);
    cudaGetSymbolAddress((void**)&p_mem_l,  g_mem_l);
    cudaGetSymbolAddress((void**)&p_m2_h,   g_m2_h);
    cudaGetSymbolAddress((void**)&p_m2_l,   g_m2_l);

    __nv_bfloat16 *p_emb_h, *p_emb_l, *p_rpw_h, *p_rpw_l, *p_ow_h, *p_ow_l, *p_vwT_h, *p_vwT_l;
    __nv_bfloat16 *p_wc_h, *p_wc_l, *p_w1_h, *p_w1_l, *p_w2_h, *p_w2_l;
    __nv_bfloat16 *p_kvw_h, *p_kvw_l, *p_to_h, *p_to_l, *p_pw_h, *p_pw_l;
    cudaGetSymbolAddress((void**)&p_emb_h, g_emb_h);
    cudaGetSymbolAddress((void**)&p_emb_l, g_emb_l);
    cudaGetSymbolAddress((void**)&p_rpw_h, g_rpw_h);
    cudaGetSymbolAddress((void**)&p_rpw_l, g_rpw_l);
    cudaGetSymbolAddress((void**)&p_ow_h,  g_ow_h);
    cudaGetSymbolAddress((void**)&p_ow_l,  g_ow_l);
    cudaGetSymbolAddress((void**)&p_vwT_h, g_vwT_h);
    cudaGetSymbolAddress((void**)&p_vwT_l, g_vwT_l);
    cudaGetSymbolAddress((void**)&p_wc_h,  g_wc_h);
    cudaGetSymbolAddress((void**)&p_wc_l,  g_wc_l);
    cudaGetSymbolAddress((void**)&p_w1_h,  g_w1_h);
    cudaGetSymbolAddress((void**)&p_w1_l,  g_w1_l);
    cudaGetSymbolAddress((void**)&p_w2_h,  g_w2_h);
    cudaGetSymbolAddress((void**)&p_w2_l,  g_w2_l);
    cudaGetSymbolAddress((void**)&p_kvw_h, g_kvw_h);
    cudaGetSymbolAddress((void**)&p_kvw_l, g_kvw_l);
    cudaGetSymbolAddress((void**)&p_to_h,  g_to_h);
    cudaGetSymbolAddress((void**)&p_to_l,  g_to_l);
    cudaGetSymbolAddress((void**)&p_pw_h,  g_pw_h);
    cudaGetSymbolAddress((void**)&p_pw_l,  g_pw_l);

    constexpr int DD = Dq * Dq, DD4 = 4 * Dq * Dq;

    auto kA   = mma_nt<128,64,4,2,256, 0,false,false,true>;
    auto kB   = mma_nt<128,64,4,2,256, 0,true ,true ,false>;
    auto kC   = mma_nt<128,128,2,4,256, 1,false,false,true>;
    auto kD   = mma_nt<128,64,4,2,256, 0,false,true ,false>;
    auto kDrp = mma_nt<128,64,4,4,512, 0,false,true ,false>;
    constexpr int SM64  = (128 + 64)  * PADK * 2 * NSTG;
    constexpr int SM128 = (128 + 128) * PADK * 2 * NSTG;
    cudaFuncSetAttribute(kA,   cudaFuncAttributeMaxDynamicSharedMemorySize, SM64);
    cudaFuncSetAttribute(kB,   cudaFuncAttributeMaxDynamicSharedMemorySize, SM64);
    cudaFuncSetAttribute(kC,   cudaFuncAttributeMaxDynamicSharedMemorySize, SM128);
    cudaFuncSetAttribute(kD,   cudaFuncAttributeMaxDynamicSharedMemorySize, SM64);
    cudaFuncSetAttribute(kDrp, cudaFuncAttributeMaxDynamicSharedMemorySize, SM64);

    static cudaStream_t s2 = nullptr;
    static cudaEvent_t e0 = nullptr, e1 = nullptr, e2 = nullptr;
    if (!s2) {
        cudaStreamCreateWithFlags(&s2, cudaStreamNonBlocking);
        cudaEventCreateWithFlags(&e0, cudaEventDisableTiming);
        cudaEventCreateWithFlags(&e1, cudaEventDisableTiming);
        cudaEventCreateWithFlags(&e2, cudaEventDisableTiming);
    }

    // ---- fork ----
    cudaEventRecord(e0, 0);
    cudaStreamWaitEvent(s2, e0, 0);

    // S2 phase 1: everything layer-0 needs (fold, ow/vwT/w1[0]/w2[0] splits, Wc both, cb)
    fold_prep_k<<<dim3(16,16,Lq), 256, 0, s2>>>(ly_vw, ly_ow, ly_vb, ly_ob, p_vwT, p_cb);
    {
        SplitArgs sa;
        int s = 0, tot = 0;
        auto add = [&](const float* src, __nv_bfloat16* h, __nv_bfloat16* l, int n4) {
            sa.seg[s++] = SplitSeg{src, h, l, n4}; tot += n4;
        };
        for (int l = 0; l < Lq; l++) {
            add(ly_ow + (size_t)l * DD,  p_ow_h + (size_t)l * DD,  p_ow_l + (size_t)l * DD,  DD/4);
            add(p_vwT + (size_t)l * DD,  p_vwT_h + (size_t)l * DD, p_vwT_l + (size_t)l * DD, DD/4);
        }
        add(ly_w1, p_w1_h, p_w1_l, DD4/4);   // layer 0
        add(ly_w2, p_w2_h, p_w2_l, DD4/4);   // layer 0
        sa.total = tot;
        split_all4_k<<<(tot + 255) / 256, 256, 0, s2>>>(sa);
    }
    for (int l = 0; l < Lq; l++)
        kA<<<dim3(Dq/64, Dq/128), 256, SM64, s2>>>(
            p_ow_h + (size_t)l*DD, p_ow_l + (size_t)l*DD,
            p_vwT_h + (size_t)l*DD, p_vwT_l + (size_t)l*DD,
            p_zero, nullptr, nullptr, p_wc_h + (size_t)l*DD, p_wc_l + (size_t)l*DD, Dq, Dq, Dq);
    cudaEventRecord(e1, s2);

    // S2 phase 2: later-needed weights + small prep
    {
        SplitArgs sa;
        int s = 0, tot = 0;
        auto add = [&](const float* src, __nv_bfloat16* h, __nv_bfloat16* l, int n4) {
            sa.seg[s++] = SplitSeg{src, h, l, n4}; tot += n4;
        };
        add(ly_w1 + (size_t)DD4, p_w1_h + (size_t)DD4, p_w1_l + (size_t)DD4, DD4/4);  // layer 1
        add(ly_w2 + (size_t)DD4, p_w2_h + (size_t)DD4, p_w2_l + (size_t)DD4, DD4/4);  // layer 1
        add(t_kw,   p_kvw_h,      p_kvw_l,      DD/4);
        add(t_vw,   p_kvw_h + DD, p_kvw_l + DD, DD/4);
        add(t_ow,   p_to_h,       p_to_l,       DD/4);
        add(proj_w, p_pw_h,       p_pw_l,       (HLLMq * Dq)/4);
        sa.total = tot;
        split_all4_k<<<(tot + 255) / 256, 256, 0, s2>>>(sa);
    }
    gemm_nt<0,true,false><<<dim3(Dq/64, 1), 256, 0, s2>>>(mem_q, t_qw, t_qb, p_q, nullptr, nullptr,
                                                          Mq, Dq, Dq);
    pack_kvb_k<<<4, 256, 0, s2>>>(t_kb, t_vb);
    noedge_k<<<Bq, 256, 0, s2>>>(edge_mask);
    cudaEventRecord(e2, s2);

    // S0: emb/rpw split -> relation projection -> sims/top-k/agg
    {
        SplitArgs sa;
        sa.seg[0] = SplitSeg{rel_emb, p_emb_h, p_emb_l, (Rq * RDq)/4};
        sa.seg[1] = SplitSeg{rp_w,    p_rpw_h, p_rpw_l, (Dq * RDq)/4};
        sa.total = (Rq * RDq + Dq * RDq)/4;
        split_all4_k<<<(sa.total + 255) / 256, 256>>>(sa);
    }
    kDrp<<<dim3(Dq/64, RPAD/128), 512, SM64>>>(
        p_emb_h, p_emb_l, p_rpw_h, p_rpw_l, rp_b, nullptr, p_proj, nullptr, nullptr,
        RPAD, Dq, RDq);
    sims_agg_k<<<BEq, 256>>>(edge_ids, neigh_ids);

    // ---- join 1: layer-0 weights ready ----
    cudaStreamWaitEvent(0, e1, 0);

    for (int l = 0; l < Lq; l++) {
        if (l == 1) cudaStreamWaitEvent(0, e2, 0);   // join 2: layer-1 + later weights

        kB<<<dim3(Dq/64, BEq/128), 256, SM64>>>(
            p_agg_h, p_agg_l, p_wc_h + (size_t)l*DD, p_wc_l + (size_t)l*DD,
            p_cb + l*Dq, p_states, p_t2, nullptr, nullptr, BEq, Dq, Dq);
        ln_k<false><<<BEq, 256>>>(p_t2, ly_n1g + l*Dq, ly_n1b + l*Dq, nullptr,
                                  p_states, p_st_h, p_st_l);

        kC<<<dim3(4*Dq/128, BEq/128), 256, SM128>>>(
            p_st_h, p_st_l, p_w1_h + (size_t)l*DD4, p_w1_l + (size_t)l*DD4,
            ly_b1 + l*4*Dq, nullptr, nullptr, p_hid_h, p_hid_l, BEq, 4*Dq, Dq);

        kB<<<dim3(Dq/64, BEq/128), 256, SM64>>>(
            p_hid_h, p_hid_l, p_w2_h + (size_t)l*DD4, p_w2_l + (size_t)l*DD4,
            ly_b2 + l*Dq, p_states, p_t2, nullptr, nullptr, BEq, Dq, 4*Dq);
        ln_k<true><<<BEq, 256>>>(p_t2, ly_n2g + l*Dq, ly_n2b + l*Dq, edge_mask,
                                 p_states, p_st_h, p_st_l);
    }

    // tokenizer K|V projection (combined)
    kD<<<dim3(2*Dq/64, BEq/128), 256, SM64>>>(
        p_st_h, p_st_l, p_kvw_h, p_kvw_l, p_kvb, nullptr, p_kv, nullptr, nullptr, BEq, 2*Dq, Dq);

    // attention + output proj + masking
    attn_k<<<Bq * Mq * Hq, 256>>>(edge_mask);
    kD<<<dim3(Dq/64, (Bq*Mq)/128), 256, SM64>>>(
        p_mem_h, p_mem_l, p_to_h, p_to_l, t_ob, nullptr, p_mem2, nullptr, nullptr, Bq*Mq, Dq, Dq);
    memmask_k<<<(Bq*Mq*Dq)/256, 256>>>();

    // LLM projection -> d_out
    kD<<<dim3(HLLMq/64, (Bq*Mq)/128), 256, SM64>>>(
        p_m2_h, p_m2_l, p_pw_h, p_pw_l, proj_b, nullptr, out, nullptr, nullptr, Bq*Mq, HLLMq, Dq);
}